// round 8
// baseline (speedup 1.0000x reference)
#include <cuda_runtime.h>

#define NB 4
#define PRE 512
#define NC 2048
#define TANCH 261120
#define NBIN 8192
#define CANDCAP 2048
#define NBLK 264
#define NINF __int_as_float(0xff800000)

// ---------------- scratch (device globals; zero-initialized) --------------
__device__ int g_hist[16][NBIN];
__device__ int g_ccnt[16];
__device__ int g_segarr[16];                      // per-segment barrier counters
__device__ int g_imgarr[NB];                      // per-image merge barrier
__device__ int g_maskdone[NB];                    // per-image mask completion
__device__ unsigned long long g_rowany[NB][32];   // per-row "has suppression bits"
__device__ unsigned long long g_cand[16][CANDCAP];
__device__ float g_box[NB][NC][5];                // pos-indexed
__device__ float g_geom[NB][NC][16];              // pos-indexed: corners, area, c, r, AABB
__device__ unsigned long long g_key[NB][NC];
__device__ int g_perm[NB][NC];                    // sorted rank -> pos
__device__ unsigned char g_svalid[NB][NC];        // sorted order
__device__ float g_sscore[NB][NC];                // sorted order
__device__ unsigned long long g_mask[NB][NC][32]; // lower-tri words stay 0

__device__ const int c_aoff[4] = {0, 196608, 245760, 258048};
__device__ const int c_segblk[4] = {48, 12, 4, 2};   // producer blocks per level

__device__ __forceinline__ unsigned fflip(float f) {
    unsigned u = __float_as_uint(f);
    return (u & 0x80000000u) ? ~u : (u | 0x80000000u);
}
__device__ __forceinline__ float funflip(unsigned u) {
    return __uint_as_float((u & 0x80000000u) ? (u ^ 0x80000000u) : ~u);
}

// block mapping: 66 blocks per image
__device__ __forceinline__ void map_block(int bx, int& b, int& lvl, int& c0, int& n) {
    b = bx / 66;
    int t = bx % 66;
    if (t < 48)      { lvl = 0; c0 = t * 4096;        n = 4096; }
    else if (t < 60) { lvl = 1; c0 = (t - 48) * 4096; n = 4096; }
    else if (t < 64) { lvl = 2; c0 = (t - 60) * 3072; n = 3072; }
    else             { lvl = 3; c0 = (t - 64) * 1536; n = 1536; }
}

__device__ __forceinline__ void hist_add(int* h, unsigned bin) {
    unsigned m = __match_any_sync(0xffffffffu, bin);
    int leader = __ffs(m) - 1;
    if ((threadIdx.x & 31) == leader) atomicAdd(&h[bin], __popc(m));
}

// ------------- stage 1 (fused): hist -> seg barrier -> thresh -> collect ---
// (g_hist / g_ccnt / g_segarr were re-zeroed by the previous replay's stage 2)
__global__ __launch_bounds__(256) void select_kernel(const float* __restrict__ o0,
                                                     const float* __restrict__ o1,
                                                     const float* __restrict__ o2,
                                                     const float* __restrict__ o3) {
    __shared__ int h[NBIN];
    for (int i = threadIdx.x; i < NBIN; i += 256) h[i] = 0;
    __syncthreads();
    int b, lvl, c0, n;
    map_block(blockIdx.x, b, lvl, c0, n);
    const float* base = lvl == 0 ? o0 : lvl == 1 ? o1 : lvl == 2 ? o2 : o3;
    int H = 256 >> lvl, HW = H * H;
    int NL = 3 * HW;
    int seg = b * 4 + lvl;
    const float4* p4 = (const float4*)(base + (long long)b * NL + c0);
    int n4 = n >> 2;

    for (int m = threadIdx.x; m < n4; m += 256) {
        float4 v = p4[m];
        hist_add(h, fflip(v.x) >> 19);
        hist_add(h, fflip(v.y) >> 19);
        hist_add(h, fflip(v.z) >> 19);
        hist_add(h, fflip(v.w) >> 19);
    }
    __syncthreads();
    for (int i = threadIdx.x; i < NBIN; i += 256)
        if (h[i]) atomicAdd(&g_hist[seg][i], h[i]);

    // per-segment barrier
    __syncthreads();
    if (threadIdx.x == 0) {
        __threadfence();
        atomicAdd(&g_segarr[seg], 1);
        int need = c_segblk[lvl];
        while (atomicAdd(&g_segarr[seg], 0) < need) {}
        __threadfence();
    }
    __syncthreads();

    // threshold: 32 bins/thread cached in registers
    __shared__ int part[256];
    __shared__ int s_c, s_cum;
    __shared__ unsigned s_th;
    int loc[32];
    {
        int t = threadIdx.x;
        int s = 0;
#pragma unroll
        for (int k = 0; k < 32; k++) {
            loc[k] = __ldcg(&g_hist[seg][NBIN - 1 - t * 32 - k]);
            s += loc[k];
        }
        part[t] = s;
    }
    __syncthreads();
    if (threadIdx.x == 0) {
        int cum = 0, c = 255;
        for (int q = 0; q < 256; q++) {
            if (cum + part[q] >= PRE) { c = q; break; }
            cum += part[q];
        }
        s_c = c; s_cum = cum;
    }
    __syncthreads();
    if (threadIdx.x == s_c) {
        int c2 = s_cum, th = 0;
#pragma unroll
        for (int k = 0; k < 32; k++) {
            int bin = NBIN - 1 - threadIdx.x * 32 - k;
            c2 += loc[k];
            if (c2 >= PRE) { th = bin; break; }
        }
        s_th = (unsigned)th;
    }
    __syncthreads();
    unsigned th = s_th;

    for (int m = threadIdx.x; m < n4; m += 256) {
        float4 v = p4[m];
        float vals[4] = {v.x, v.y, v.z, v.w};
#pragma unroll
        for (int s = 0; s < 4; s++) {
            unsigned u = fflip(vals[s]);
            if ((u >> 19) >= th) {
                int gm = c0 + m * 4 + s;
                int idx = (gm % HW) * 3 + gm / HW;   // (y*W+x)*A + a order
                int pos = atomicAdd(&g_ccnt[seg], 1);
                if (pos < CANDCAP)
                    g_cand[seg][pos] = (((unsigned long long)u) << 32) | (unsigned)(~idx);
            }
        }
    }
}

// ---- stage 2 (fused): sort -> top-512 -> decode + geometry -> merge -------
__device__ __forceinline__ unsigned long long merge_pick(
    const unsigned long long* A, const unsigned long long* B, int len, int i) {
    int lo = i > len ? i - len : 0;
    int hi = i < len ? i : len;
    while (lo < hi) {
        int a = (lo + hi) >> 1;
        if (A[a] > B[i - a - 1]) lo = a + 1; else hi = a;
    }
    int aa = lo, bb = i - lo;
    return (aa < len && (bb >= len || A[aa] > B[bb])) ? A[aa] : B[bb];
}

__global__ __launch_bounds__(512) void sortdecode_kernel(const float* __restrict__ d0,
                                                         const float* __restrict__ d1,
                                                         const float* __restrict__ d2,
                                                         const float* __restrict__ d3,
                                                         const float* __restrict__ anchors) {
    int seg = blockIdx.x;
    int sb = seg >> 2, slvl = seg & 3;
    __shared__ unsigned long long sk[CANDCAP];
    __shared__ unsigned long long tmp[CANDCAP];
    __shared__ int wtot[16], woff[16];
    __shared__ int s_tot;
    int tid = threadIdx.x;
    int cnt = g_ccnt[seg];
    if (cnt > CANDCAP) cnt = CANDCAP;
    int M = (cnt <= 1024) ? 1024 : CANDCAP;
    for (int i = tid; i < M; i += 512)
        sk[i] = (i < cnt) ? g_cand[seg][i] : 0ull;
    __syncthreads();
    // re-zero scratch consumed by stage 1 (for the next replay)
    if (tid == 0) { g_ccnt[seg] = 0; g_segarr[seg] = 0; }
    for (int i = tid; i < NBIN; i += 512) g_hist[seg][i] = 0;
    for (int ksz = 2; ksz <= M; ksz <<= 1) {
        for (int j = ksz >> 1; j > 0; j >>= 1) {
            for (int i = tid; i < M; i += 512) {
                int l = i ^ j;
                if (l > i) {
                    unsigned long long a = sk[i], c = sk[l];
                    bool desc = ((i & ksz) == 0);
                    if (desc ? (a < c) : (a > c)) { sk[i] = c; sk[l] = a; }
                }
            }
            __syncthreads();
        }
    }
    // decode (each of the 512 threads takes one entry)
    unsigned long long kk = sk[tid];
    float val = funflip((unsigned)(kk >> 32));
    int li = (int)(~(unsigned)(kk & 0xFFFFFFFFull));
    int sH = 256 >> slvl, sHW = sH * sH;
    int a = li % 3, cell = li / 3;
    int x = cell % sH, y = cell / sH;
    const float* dl = slvl == 0 ? d0 : slvl == 1 ? d1 : slvl == 2 ? d2 : d3;
    long long bi = ((long long)sb * 18 + a * 6) * sHW + (long long)y * sH + x;
    float dx = dl[bi], dy = dl[bi + sHW], dw = dl[bi + 2LL * sHW],
          dh = dl[bi + 3LL * sHW], ds = dl[bi + 4LL * sHW], dc = dl[bi + 5LL * sHW];
    int ta = c_aoff[slvl] + li;
    const float* an = anchors + ((long long)sb * TANCH + ta) * 5;
    float ax = an[0], ay = an[1], aw = an[2], ah = an[3], aa = an[4];
    const float LOGM = 4.135166556742356f;
    dw = fminf(dw, LOGM);
    dh = fminf(dh, LOGM);
    float bw = aw * expf(dw), bh = ah * expf(dh);
    float bcx = ax + dx * aw, bcy = ay + dy * ah;
    float ang = aa + atan2f(ds, dc);
    float sc = 0.5f + 0.5f * tanhf(0.5f * val);       // XLA logistic form
    bool vd = (bw >= 1e-3f) && (bh >= 1e-3f) && (sc >= 0.0f);

    // stable compaction: valids to front, invalids to tail
    unsigned bal = __ballot_sync(0xffffffffu, vd);
    int lane = tid & 31, w = tid >> 5;
    int prew = __popc(bal & ((1u << lane) - 1u));
    if (lane == 0) wtot[w] = __popc(bal);
    __syncthreads();
    if (tid == 0) {
        int s = 0;
        for (int q = 0; q < 16; q++) { woff[q] = s; s += wtot[q]; }
        s_tot = s;
    }
    __syncthreads();
    int vbefore = woff[w] + prew;
    int rank = vd ? vbefore : (s_tot + (tid - vbefore));
    int pos = slvl * PRE + rank;

    g_box[sb][pos][0] = bcx; g_box[sb][pos][1] = bcy;
    g_box[sb][pos][2] = bw;  g_box[sb][pos][3] = bh;
    g_box[sb][pos][4] = ang;
    unsigned u = vd ? __float_as_uint(sc) : 0u;       // score desc, pos asc tiebreak
    g_key[sb][pos] = (((unsigned long long)u) << 32) | (unsigned)(2047 - pos);

    // geometry (pos-indexed), values already in registers
    {
        float off = 8192.0f * (float)slvl;
        float cx = bcx + off, cy = bcy + off;
        float ca = cosf(ang), sa = sinf(ang);
        float hw = 0.5f * bw, hh = 0.5f * bh;
        float dxs[4] = {hw, -hw, -hw, hw};
        float dys[4] = {hh, hh, -hh, -hh};
        float xmn = 1e30f, xmx = -1e30f, ymn = 1e30f, ymx = -1e30f;
        float* gp = &g_geom[sb][pos][0];
#pragma unroll
        for (int c = 0; c < 4; c++) {
            float xx = cx + dxs[c] * ca - dys[c] * sa;
            float yy = cy + dxs[c] * sa + dys[c] * ca;
            gp[2 * c] = xx;
            gp[2 * c + 1] = yy;
            xmn = fminf(xmn, xx); xmx = fmaxf(xmx, xx);
            ymn = fminf(ymn, yy); ymx = fmaxf(ymx, yy);
        }
        gp[8] = bw * bh;
        gp[9] = cx;
        gp[10] = cy;
        gp[11] = 0.5f * sqrtf(bw * bw + bh * bh);
        gp[12] = xmn;
        gp[13] = xmx;
        gp[14] = ymn;
        gp[15] = ymx;
    }

    // ---- publish this segment's run; slvl==0 block merges its image ----
    __syncthreads();
    if (tid == 0) {
        __threadfence();
        atomicAdd(&g_imgarr[sb], 1);
    }
    if (slvl != 0) return;
    if (tid == 0) {
        while (atomicAdd(&g_imgarr[sb], 0) < 4) {}
        __threadfence();
        g_imgarr[sb] = 0;                 // reset for next replay
    }
    __syncthreads();
    // load all 4 runs (L2-hot; __ldcg to bypass possibly-stale L1)
    for (int i = tid; i < NC; i += 512) sk[i] = __ldcg(&g_key[sb][i]);
    __syncthreads();
#pragma unroll
    for (int half = 0; half < 2; half++) {
        const unsigned long long* A = sk + half * 1024;
        for (int i = tid; i < 1024; i += 512)
            tmp[half * 1024 + i] = merge_pick(A, A + 512, 512, i);
    }
    __syncthreads();
    for (int i = tid; i < NC; i += 512) {
        unsigned long long mk = merge_pick(tmp, tmp + 1024, 1024, i);
        int mpos = 2047 - (int)(unsigned)(mk & 0xFFFFFFFFull);
        unsigned mu = (unsigned)(mk >> 32);
        g_perm[sb][i] = mpos;
        g_svalid[sb][i] = mu != 0u ? 1 : 0;           // u==0 <=> invalid
        g_sscore[sb][i] = mu != 0u ? __uint_as_float(mu) : NINF;
    }
}

// -- stage 3 (fused): IoU mask; last block per image runs greedy + output ---
__device__ float inter_area(float4 pA, float4 pB, float4 qA, float4 qB) {
    float px[8], py[8], ox[8], oy[8];
    px[0] = pA.x; py[0] = pA.y; px[1] = pA.z; py[1] = pA.w;
    px[2] = pB.x; py[2] = pB.y; px[3] = pB.z; py[3] = pB.w;
    float qx[4] = {qA.x, qA.z, qB.x, qB.z};
    float qy[4] = {qA.y, qA.w, qB.y, qB.w};
    int cnt = 4;
#pragma unroll
    for (int kk = 0; kk < 4; kk++) {
        float p1x = qx[kk], p1y = qy[kk];
        int k2 = (kk + 1) & 3;
        float ex = qx[k2] - p1x, ey = qy[k2] - p1y;
        int oc = 0;
        float d0 = ex * (py[0] - p1y) - ey * (px[0] - p1x);
        float dc = d0;
        for (int i = 0; i < cnt; i++) {
            int nx = (i + 1 < cnt) ? i + 1 : 0;
            float dn = (i + 1 < cnt) ? (ex * (py[i + 1] - p1y) - ey * (px[i + 1] - p1x)) : d0;
            bool ci = dc >= 0.f, ni = dn >= 0.f;
            if (ci) { ox[oc] = px[i]; oy[oc] = py[i]; oc++; }
            if (ci != ni) {
                float den = dc - dn;
                float tt = dc / ((den == 0.f) ? 1.f : den);
                ox[oc] = px[i] + tt * (px[nx] - px[i]);
                oy[oc] = py[i] + tt * (py[nx] - py[i]);
                oc++;
            }
            dc = dn;
        }
        cnt = oc;
        if (cnt == 0) break;
        for (int i = 0; i < cnt; i++) { px[i] = ox[i]; py[i] = oy[i]; }
    }
    if (cnt < 3) return 0.f;
    float s = 0.f;
    for (int i = 0; i < cnt; i++) {
        int nx = (i + 1 < cnt) ? i + 1 : 0;
        s += px[i] * py[nx] - px[nx] * py[i];
    }
    return 0.5f * fabsf(s);
}

__global__ __launch_bounds__(256) void mask_kernel(float* __restrict__ out) {
    int grp = threadIdx.x >> 6, lane = threadIdx.x & 63;
    int tile = blockIdx.x * 4 + grp;            // 2112 tiles; block's 4 share one img
    int img = tile / 528, tri = tile % 528;
    int rb = 0, rowrem = 32;
    while (tri >= rowrem) { tri -= rowrem; rowrem--; rb++; }
    int cb = rb + tri;

    __shared__ float4 sg[4][64][4];
    __shared__ int sperm[4][64];
    __shared__ int s_old;
    __shared__ int s_keep[PRE];
    __shared__ int s_n;
    const float4* gg = (const float4*)&g_geom[img][0][0];
    sperm[grp][lane] = g_perm[img][cb * 64 + lane];
    int prow = g_perm[img][rb * 64 + lane];
    __syncthreads();
    for (int i = lane; i < 256; i += 64) {
        int box = i >> 2, k = i & 3;
        sg[grp][box][k] = gg[sperm[grp][box] * 4 + k];
    }
    __syncthreads();

    int row = rb * 64 + lane;
    float4 rA = gg[prow * 4 + 0];
    float4 rB = gg[prow * 4 + 1];
    float4 rC = gg[prow * 4 + 2];   // area, cx, cy, r
    float4 rD = gg[prow * 4 + 3];   // xmin, xmax, ymin, ymax

    // pass 1: branchless cheap filters -> survivor bitmask
    unsigned long long surv = 0;
#pragma unroll 4
    for (int j = 0; j < 64; j++) {
        float4 cC = sg[grp][j][2];
        float ddx = rC.y - cC.y, ddy = rC.z - cC.z;
        float rr = rC.w + cC.w;
        float mn = fminf(rC.x, cC.x), mx = fmaxf(rC.x, cC.x);
        bool ok = (ddx * ddx + ddy * ddy < rr * rr) && (mn > 0.7f * mx);
        surv |= ((unsigned long long)ok) << j;
    }
    if (cb == rb) surv &= (lane < 63) ? (~0ull << (lane + 1)) : 0ull;

    // pass 2: exact checks only on survivors
    unsigned long long bits = 0;
    while (surv) {
        int j = __ffsll((long long)surv) - 1;
        surv &= surv - 1;
        float4 cC = sg[grp][j][2];
        float4 cD = sg[grp][j][3];
        float S = rC.x + cC.x;
        float xl = fmaxf(rD.x, cD.x), xr = fminf(rD.y, cD.y);
        float yl = fmaxf(rD.z, cD.z), yr = fminf(rD.w, cD.w);
        float ub = fmaxf(xr - xl, 0.f) * fmaxf(yr - yl, 0.f);
        if (ub * 1.7f < S * 0.6993f) continue;              // AABB bound (margin)
        float inter = inter_area(rA, rB, sg[grp][j][0], sg[grp][j][1]);
        float iou = inter / (S - inter + 1e-7f);
        if (iou > 0.7f) bits |= (1ull << j);
    }
    g_mask[img][row][cb] = bits;
    if (bits)
        atomicOr(&g_rowany[img][row >> 6], 1ull << (row & 63));

    // ---- last-block-done detection for this image ----
    __threadfence();
    __syncthreads();
    if (threadIdx.x == 0) s_old = atomicAdd(&g_maskdone[img], 1);
    __syncthreads();
    if (s_old != 131) return;
    // this block is the 132nd (last) for img: run greedy + output
    __threadfence();
    if (threadIdx.x == 0) g_maskdone[img] = 0;     // reset for next replay
    if (threadIdx.x < 32) {
        int gl = threadIdx.x;
        unsigned long long remv = 0;
        const unsigned long long* vp = (const unsigned long long*)&g_svalid[img][gl * 64];
#pragma unroll
        for (int q = 0; q < 8; q++) {
            unsigned long long w8 = vp[q];
#pragma unroll
            for (int kk = 0; kk < 8; kk++)
                if (((w8 >> (kk * 8)) & 0xffull) == 0ull)
                    remv |= (1ull << (q * 8 + kk));
        }
        unsigned long long ra = __ldcg(&g_rowany[img][gl]);
        g_rowany[img][gl] = 0ull;                  // reset for next replay
        int n = 0;
        for (int i = 0; i < NC; i++) {
            unsigned long long w = __shfl_sync(0xffffffffu, remv, (i >> 6));
            if (!((w >> (i & 63)) & 1ull)) {
                if (gl == 0) s_keep[n] = i;
                n++;
                unsigned long long raw = __shfl_sync(0xffffffffu, ra, (i >> 6));
                if ((raw >> (i & 63)) & 1ull)
                    remv |= __ldcg(&g_mask[img][i][gl]);   // rare: rows with bits
                if (n >= PRE) break;
            }
        }
        if (gl == 0) s_n = n;
    }
    __syncthreads();
    int n = s_n;
#pragma unroll
    for (int half = 0; half < 2; half++) {
        int slot = threadIdx.x + half * 256;
        float v0 = 0, v1 = 0, v2 = 0, v3 = 0, v4 = 0, sc = 0;
        if (slot < n) {
            int i = s_keep[slot];
            int pos = g_perm[img][i];
            v0 = g_box[img][pos][0]; v1 = g_box[img][pos][1];
            v2 = g_box[img][pos][2]; v3 = g_box[img][pos][3];
            v4 = g_box[img][pos][4];
            sc = g_sscore[img][i];
        }
        float* ob = out + ((long long)img * PRE + slot) * 5;
        ob[0] = v0; ob[1] = v1; ob[2] = v2; ob[3] = v3; ob[4] = v4;
        out[NB * PRE * 5 + img * PRE + slot] = sc;
    }
}

extern "C" void kernel_launch(void* const* d_in, const int* in_sizes, int n_in,
                              void* d_out, int out_size) {
    const float* obj[4] = {0, 0, 0, 0};
    const float* dlt[4] = {0, 0, 0, 0};
    const float* anch = 0;
    const int osz[4] = {786432, 196608, 49152, 12288};
    const int dsz[4] = {4718592, 1179648, 294912, 73728};
    for (int i = 0; i < n_in; i++) {
        int s = in_sizes[i];
        const float* p = (const float*)d_in[i];
        if (s == 5222400) { anch = p; continue; }
        for (int l = 0; l < 4; l++) {
            if (s == osz[l]) obj[l] = p;
            else if (s == dsz[l]) dlt[l] = p;
        }
    }
    select_kernel<<<NBLK, 256>>>(obj[0], obj[1], obj[2], obj[3]);
    sortdecode_kernel<<<16, 512>>>(dlt[0], dlt[1], dlt[2], dlt[3], anch);
    mask_kernel<<<528, 256>>>((float*)d_out);
}

// round 9
// speedup vs baseline: 1.1527x; 1.1527x over previous
#include <cuda_runtime.h>

#define NB 4
#define PRE 512
#define NC 2048
#define TANCH 261120
#define NBIN 4096
#define SHIFT 20
#define CANDCAP 2048
#define NBLK 264
#define NINF __int_as_float(0xff800000)

// ---------------- scratch (device globals; zero-initialized) --------------
__device__ int g_hist[16][NBIN];
__device__ int g_ccnt[16];
__device__ int g_segarr[16];                      // per-segment barrier counters
__device__ unsigned long long g_rowany[NB][32];   // per-row "has suppression bits"
__device__ unsigned long long g_cand[16][CANDCAP];
__device__ float g_box[NB][NC][5];                // pos-indexed
__device__ float g_score[NB][NC];                 // pos-indexed
__device__ unsigned char g_valid[NB][NC];         // pos-indexed
__device__ float g_geom[NB][NC][16];              // pos-indexed
__device__ unsigned long long g_key[NB][NC];
__device__ int g_perm[NB][NC];                    // sorted rank -> pos
__device__ unsigned char g_svalid[NB][NC];        // sorted order
__device__ float g_sscore[NB][NC];                // sorted order
__device__ unsigned long long g_mask[NB][NC][32];

__device__ const int c_aoff[4] = {0, 196608, 245760, 258048};
__device__ const int c_segblk[4] = {48, 12, 4, 2};   // producer blocks per level

__device__ __forceinline__ unsigned fflip(float f) {
    unsigned u = __float_as_uint(f);
    return (u & 0x80000000u) ? ~u : (u | 0x80000000u);
}
__device__ __forceinline__ float funflip(unsigned u) {
    return __uint_as_float((u & 0x80000000u) ? (u ^ 0x80000000u) : ~u);
}

// block mapping: 66 blocks per image
__device__ __forceinline__ void map_block(int bx, int& b, int& lvl, int& c0, int& n) {
    b = bx / 66;
    int t = bx % 66;
    if (t < 48)      { lvl = 0; c0 = t * 4096;        n = 4096; }
    else if (t < 60) { lvl = 1; c0 = (t - 48) * 4096; n = 4096; }
    else if (t < 64) { lvl = 2; c0 = (t - 60) * 3072; n = 3072; }
    else             { lvl = 3; c0 = (t - 64) * 1536; n = 1536; }
}

__device__ __forceinline__ void hist_add(int* h, unsigned bin) {
    unsigned m = __match_any_sync(0xffffffffu, bin);
    int leader = __ffs(m) - 1;
    if ((threadIdx.x & 31) == leader) atomicAdd(&h[bin], __popc(m));
}

// ---------------- stage 0: tiny init (per-replay resets) ------------------
__global__ void init_kernel() {
    int t = threadIdx.x;
    if (t < 16) g_segarr[t] = 0;
    if (t < 128) ((unsigned long long*)g_rowany)[t] = 0ull;
}

// ------------- stage 1 (fused): hist -> seg barrier -> thresh -> collect ---
__global__ __launch_bounds__(512) void select_kernel(const float* __restrict__ o0,
                                                     const float* __restrict__ o1,
                                                     const float* __restrict__ o2,
                                                     const float* __restrict__ o3) {
    __shared__ int h[NBIN];
    int tid = threadIdx.x;
    for (int i = tid; i < NBIN; i += 512) h[i] = 0;
    __syncthreads();
    int b, lvl, c0, n;
    map_block(blockIdx.x, b, lvl, c0, n);
    const float* base = lvl == 0 ? o0 : lvl == 1 ? o1 : lvl == 2 ? o2 : o3;
    int H = 256 >> lvl, HW = H * H;
    int NL = 3 * HW;
    int seg = b * 4 + lvl;
    const float4* p4 = (const float4*)(base + (long long)b * NL + c0);
    int n4 = n >> 2;

    for (int m = tid; m < n4; m += 512) {
        float4 v = p4[m];
        hist_add(h, fflip(v.x) >> SHIFT);
        hist_add(h, fflip(v.y) >> SHIFT);
        hist_add(h, fflip(v.z) >> SHIFT);
        hist_add(h, fflip(v.w) >> SHIFT);
    }
    __syncthreads();
    for (int i = tid; i < NBIN; i += 512)
        if (h[i]) atomicAdd(&g_hist[seg][i], h[i]);

    // per-segment barrier: wait only for this segment's producer blocks
    __syncthreads();
    if (tid == 0) {
        __threadfence();
        atomicAdd(&g_segarr[seg], 1);
        int need = c_segblk[lvl];
        while (atomicAdd(&g_segarr[seg], 0) < need) {}
        __threadfence();
    }
    __syncthreads();

    // hierarchical threshold search: 8 bins/thread (descending), warp sums
    __shared__ int wsum[16];
    __shared__ int s_w, s_cum;
    __shared__ unsigned s_th;
    int loc[8];
    int lsum = 0;
#pragma unroll
    for (int k = 0; k < 8; k++) {
        loc[k] = __ldcg(&g_hist[seg][NBIN - 1 - tid * 8 - k]);
        lsum += loc[k];
    }
    int lane = tid & 31, w = tid >> 5;
    {
        int wl = lsum;
#pragma unroll
        for (int off = 16; off > 0; off >>= 1)
            wl += __shfl_down_sync(0xffffffffu, wl, off);
        if (lane == 0) wsum[w] = wl;
    }
    __syncthreads();
    if (tid == 0) {
        int cum = 0, cw = 15;
        for (int q = 0; q < 16; q++) {
            if (cum + wsum[q] >= PRE) { cw = q; break; }
            cum += wsum[q];
        }
        s_w = cw; s_cum = cum;
    }
    __syncthreads();
    if (w == s_w) {
        int pre = lsum;
#pragma unroll
        for (int off = 1; off < 32; off <<= 1) {
            int v = __shfl_up_sync(0xffffffffu, pre, off);
            if (lane >= off) pre += v;
        }
        int incl = s_cum + pre;                       // inclusive cumulative
        unsigned ball = __ballot_sync(0xffffffffu, incl >= PRE);
        int first = __ffs(ball) - 1;
        if (lane == first) {
            int c2 = incl - lsum;                     // exclusive cumulative
            unsigned th = 0;
#pragma unroll
            for (int k = 0; k < 8; k++) {
                c2 += loc[k];
                if (c2 >= PRE) { th = (unsigned)(NBIN - 1 - tid * 8 - k); break; }
            }
            s_th = th;
        }
    }
    __syncthreads();
    unsigned th = s_th;

    for (int m = tid; m < n4; m += 512) {
        float4 v = p4[m];
        float vals[4] = {v.x, v.y, v.z, v.w};
#pragma unroll
        for (int s = 0; s < 4; s++) {
            unsigned u = fflip(vals[s]);
            if ((u >> SHIFT) >= th) {
                int gm = c0 + m * 4 + s;
                int idx = (gm % HW) * 3 + gm / HW;   // (y*W+x)*A + a order
                int pos = atomicAdd(&g_ccnt[seg], 1);
                if (pos < CANDCAP)
                    g_cand[seg][pos] = (((unsigned long long)u) << 32) | (unsigned)(~idx);
            }
        }
    }
}

// ------- stage 2: per-segment sort -> exact top-512 -> decode + geometry ---
__global__ __launch_bounds__(512) void sortdecode_kernel(const float* __restrict__ d0,
                                                         const float* __restrict__ d1,
                                                         const float* __restrict__ d2,
                                                         const float* __restrict__ d3,
                                                         const float* __restrict__ anchors) {
    int seg = blockIdx.x;
    int sb = seg >> 2, slvl = seg & 3;
    __shared__ unsigned long long sk[CANDCAP];
    __shared__ int wtot[16], woff[16];
    __shared__ int s_tot;
    int tid = threadIdx.x;
    int cnt = g_ccnt[seg];
    if (cnt > CANDCAP) cnt = CANDCAP;
    int M = (cnt <= 1024) ? 1024 : CANDCAP;
    for (int i = tid; i < M; i += 512)
        sk[i] = (i < cnt) ? g_cand[seg][i] : 0ull;
    __syncthreads();
    // re-zero scratch for next replay
    if (tid == 0) { g_ccnt[seg] = 0; g_segarr[seg] = 0; }
    for (int i = tid; i < NBIN; i += 512) g_hist[seg][i] = 0;
    for (int ksz = 2; ksz <= M; ksz <<= 1) {
        for (int j = ksz >> 1; j > 0; j >>= 1) {
            for (int i = tid; i < M; i += 512) {
                int l = i ^ j;
                if (l > i) {
                    unsigned long long a = sk[i], c = sk[l];
                    bool desc = ((i & ksz) == 0);
                    if (desc ? (a < c) : (a > c)) { sk[i] = c; sk[l] = a; }
                }
            }
            __syncthreads();
        }
    }
    // decode (each of the 512 threads takes one entry)
    unsigned long long kk = sk[tid];
    float val = funflip((unsigned)(kk >> 32));
    int li = (int)(~(unsigned)(kk & 0xFFFFFFFFull));
    int sH = 256 >> slvl, sHW = sH * sH;
    int a = li % 3, cell = li / 3;
    int x = cell % sH, y = cell / sH;
    const float* dl = slvl == 0 ? d0 : slvl == 1 ? d1 : slvl == 2 ? d2 : d3;
    long long bi = ((long long)sb * 18 + a * 6) * sHW + (long long)y * sH + x;
    float dx = dl[bi], dy = dl[bi + sHW], dw = dl[bi + 2LL * sHW],
          dh = dl[bi + 3LL * sHW], ds = dl[bi + 4LL * sHW], dc = dl[bi + 5LL * sHW];
    int ta = c_aoff[slvl] + li;
    const float* an = anchors + ((long long)sb * TANCH + ta) * 5;
    float ax = an[0], ay = an[1], aw = an[2], ah = an[3], aa = an[4];
    const float LOGM = 4.135166556742356f;
    dw = fminf(dw, LOGM);
    dh = fminf(dh, LOGM);
    float bw = aw * expf(dw), bh = ah * expf(dh);
    float bcx = ax + dx * aw, bcy = ay + dy * ah;
    float ang = aa + atan2f(ds, dc);
    float sc = 0.5f + 0.5f * tanhf(0.5f * val);       // XLA logistic form
    bool vd = (bw >= 1e-3f) && (bh >= 1e-3f) && (sc >= 0.0f);

    // stable compaction: valids to front, invalids to tail, order preserved
    unsigned bal = __ballot_sync(0xffffffffu, vd);
    int lane = tid & 31, w = tid >> 5;
    int prew = __popc(bal & ((1u << lane) - 1u));
    if (lane == 0) wtot[w] = __popc(bal);
    __syncthreads();
    if (tid == 0) {
        int s = 0;
        for (int q = 0; q < 16; q++) { woff[q] = s; s += wtot[q]; }
        s_tot = s;
    }
    __syncthreads();
    int vbefore = woff[w] + prew;
    int rank = vd ? vbefore : (s_tot + (tid - vbefore));
    int pos = slvl * PRE + rank;

    g_box[sb][pos][0] = bcx; g_box[sb][pos][1] = bcy;
    g_box[sb][pos][2] = bw;  g_box[sb][pos][3] = bh;
    g_box[sb][pos][4] = ang;
    g_score[sb][pos] = sc;
    g_valid[sb][pos] = vd ? 1 : 0;
    unsigned u = vd ? __float_as_uint(sc) : 0u;       // score desc, pos asc tiebreak
    g_key[sb][pos] = (((unsigned long long)u) << 32) | (unsigned)(2047 - pos);

    // geometry (pos-indexed), values already in registers
    {
        float off = 8192.0f * (float)slvl;
        float cx = bcx + off, cy = bcy + off;
        float ca = cosf(ang), sa = sinf(ang);
        float hw = 0.5f * bw, hh = 0.5f * bh;
        float dxs[4] = {hw, -hw, -hw, hw};
        float dys[4] = {hh, hh, -hh, -hh};
        float xmn = 1e30f, xmx = -1e30f, ymn = 1e30f, ymx = -1e30f;
        float* gp = &g_geom[sb][pos][0];
#pragma unroll
        for (int c = 0; c < 4; c++) {
            float xx = cx + dxs[c] * ca - dys[c] * sa;
            float yy = cy + dxs[c] * sa + dys[c] * ca;
            gp[2 * c] = xx;
            gp[2 * c + 1] = yy;
            xmn = fminf(xmn, xx); xmx = fmaxf(xmx, xx);
            ymn = fminf(ymn, yy); ymx = fmaxf(ymx, yy);
        }
        gp[8] = bw * bh;
        gp[9] = cx;
        gp[10] = cy;
        gp[11] = 0.5f * sqrtf(bw * bw + bh * bh);
        gp[12] = xmn;
        gp[13] = xmx;
        gp[14] = ymn;
        gp[15] = ymx;
    }
}

// -------- stage 3: 4-way merge -> permutation (tiny) -----------------------
__device__ __forceinline__ unsigned long long merge_pick(
    const unsigned long long* A, const unsigned long long* B, int len, int i) {
    int lo = i > len ? i - len : 0;
    int hi = i < len ? i : len;
    while (lo < hi) {
        int a = (lo + hi) >> 1;
        if (A[a] > B[i - a - 1]) lo = a + 1; else hi = a;
    }
    int aa = lo, bb = i - lo;
    return (aa < len && (bb >= len || A[aa] > B[bb])) ? A[aa] : B[bb];
}

__global__ __launch_bounds__(512) void merge_kernel() {
    int b = blockIdx.x;
    __shared__ unsigned long long sk[NC];
    __shared__ unsigned long long tmp[NC];
    int tid = threadIdx.x;
    for (int i = tid; i < NC; i += 512) sk[i] = g_key[b][i];
    __syncthreads();
#pragma unroll
    for (int half = 0; half < 2; half++) {
        const unsigned long long* A = sk + half * 1024;
        for (int i = tid; i < 1024; i += 512)
            tmp[half * 1024 + i] = merge_pick(A, A + 512, 512, i);
    }
    __syncthreads();
    for (int i = tid; i < 2048; i += 512) {
        unsigned long long kk = merge_pick(tmp, tmp + 1024, 1024, i);
        int pos = 2047 - (int)(unsigned)(kk & 0xFFFFFFFFull);
        g_perm[b][i] = pos;
        unsigned char vd = g_valid[b][pos];
        g_svalid[b][i] = vd;
        g_sscore[b][i] = vd ? g_score[b][pos] : NINF;
    }
}

// ---------------- stage 4: rotated IoU suppression bitmask -----------------
__device__ float inter_area(float4 pA, float4 pB, float4 qA, float4 qB) {
    float px[8], py[8], ox[8], oy[8];
    px[0] = pA.x; py[0] = pA.y; px[1] = pA.z; py[1] = pA.w;
    px[2] = pB.x; py[2] = pB.y; px[3] = pB.z; py[3] = pB.w;
    float qx[4] = {qA.x, qA.z, qB.x, qB.z};
    float qy[4] = {qA.y, qA.w, qB.y, qB.w};
    int cnt = 4;
#pragma unroll
    for (int kk = 0; kk < 4; kk++) {
        float p1x = qx[kk], p1y = qy[kk];
        int k2 = (kk + 1) & 3;
        float ex = qx[k2] - p1x, ey = qy[k2] - p1y;
        int oc = 0;
        float d0 = ex * (py[0] - p1y) - ey * (px[0] - p1x);
        float dc = d0;
        for (int i = 0; i < cnt; i++) {
            int nx = (i + 1 < cnt) ? i + 1 : 0;
            float dn = (i + 1 < cnt) ? (ex * (py[i + 1] - p1y) - ey * (px[i + 1] - p1x)) : d0;
            bool ci = dc >= 0.f, ni = dn >= 0.f;
            if (ci) { ox[oc] = px[i]; oy[oc] = py[i]; oc++; }
            if (ci != ni) {
                float den = dc - dn;
                float tt = dc / ((den == 0.f) ? 1.f : den);
                ox[oc] = px[i] + tt * (px[nx] - px[i]);
                oy[oc] = py[i] + tt * (py[nx] - py[i]);
                oc++;
            }
            dc = dn;
        }
        cnt = oc;
        if (cnt == 0) break;
        for (int i = 0; i < cnt; i++) { px[i] = ox[i]; py[i] = oy[i]; }
    }
    if (cnt < 3) return 0.f;
    float s = 0.f;
    for (int i = 0; i < cnt; i++) {
        int nx = (i + 1 < cnt) ? i + 1 : 0;
        s += px[i] * py[nx] - px[nx] * py[i];
    }
    return 0.5f * fabsf(s);
}

__global__ __launch_bounds__(256) void mask_kernel() {
    int grp = threadIdx.x >> 6, lane = threadIdx.x & 63;
    int tile = blockIdx.x * 4 + grp;            // 2112 tiles total
    int img = tile / 528, tri = tile % 528;
    int rb = 0, rowrem = 32;
    while (tri >= rowrem) { tri -= rowrem; rowrem--; rb++; }
    int cb = rb + tri;

    __shared__ float4 sg[4][64][4];
    __shared__ int sperm[4][64];
    const float4* gg = (const float4*)&g_geom[img][0][0];
    sperm[grp][lane] = g_perm[img][cb * 64 + lane];
    int prow = g_perm[img][rb * 64 + lane];
    __syncthreads();
    for (int i = lane; i < 256; i += 64) {
        int box = i >> 2, k = i & 3;
        sg[grp][box][k] = gg[sperm[grp][box] * 4 + k];
    }
    __syncthreads();

    int row = rb * 64 + lane;
    float4 rA = gg[prow * 4 + 0];
    float4 rB = gg[prow * 4 + 1];
    float4 rC = gg[prow * 4 + 2];   // area, cx, cy, r
    float4 rD = gg[prow * 4 + 3];   // xmin, xmax, ymin, ymax

    // pass 1: branchless cheap filters -> survivor bitmask
    unsigned long long surv = 0;
#pragma unroll 4
    for (int j = 0; j < 64; j++) {
        float4 cC = sg[grp][j][2];
        float ddx = rC.y - cC.y, ddy = rC.z - cC.z;
        float rr = rC.w + cC.w;
        float mn = fminf(rC.x, cC.x), mx = fmaxf(rC.x, cC.x);
        bool ok = (ddx * ddx + ddy * ddy < rr * rr) && (mn > 0.7f * mx);
        surv |= ((unsigned long long)ok) << j;
    }
    if (cb == rb) surv &= (lane < 63) ? (~0ull << (lane + 1)) : 0ull;

    // pass 2: exact checks only on survivors
    unsigned long long bits = 0;
    while (surv) {
        int j = __ffsll((long long)surv) - 1;
        surv &= surv - 1;
        float4 cC = sg[grp][j][2];
        float4 cD = sg[grp][j][3];
        float S = rC.x + cC.x;
        float xl = fmaxf(rD.x, cD.x), xr = fminf(rD.y, cD.y);
        float yl = fmaxf(rD.z, cD.z), yr = fminf(rD.w, cD.w);
        float ub = fmaxf(xr - xl, 0.f) * fmaxf(yr - yl, 0.f);
        if (ub * 1.7f < S * 0.6993f) continue;              // AABB bound (margin)
        float inter = inter_area(rA, rB, sg[grp][j][0], sg[grp][j][1]);
        float iou = inter / (S - inter + 1e-7f);
        if (iou > 0.7f) bits |= (1ull << j);
    }
    g_mask[img][row][cb] = bits;
    if (bits)
        atomicOr(&g_rowany[img][row >> 6], 1ull << (row & 63));
}

// ---------- stage 5 (fused): greedy scan + padded output write ------------
__global__ __launch_bounds__(512) void greedy_out_kernel(float* __restrict__ out) {
    int b = blockIdx.x;
    int tid = threadIdx.x;
    __shared__ int keep[PRE];
    __shared__ int s_n;
    if (tid < 32) {
        int lane = tid;
        unsigned long long remv = 0;
        const unsigned long long* vp = (const unsigned long long*)&g_svalid[b][lane * 64];
#pragma unroll
        for (int q = 0; q < 8; q++) {
            unsigned long long w8 = vp[q];
#pragma unroll
            for (int kk = 0; kk < 8; kk++)
                if (((w8 >> (kk * 8)) & 0xffull) == 0ull)
                    remv |= (1ull << (q * 8 + kk));
        }
        unsigned long long ra = g_rowany[b][lane];   // lane's 64-row "has bits" word
        int n = 0;
        for (int i = 0; i < NC; i++) {
            unsigned long long w = __shfl_sync(0xffffffffu, remv, (i >> 6));
            if (!((w >> (i & 63)) & 1ull)) {
                if (lane == 0) keep[n] = i;
                n++;
                unsigned long long raw = __shfl_sync(0xffffffffu, ra, (i >> 6));
                if ((raw >> (i & 63)) & 1ull)
                    remv |= g_mask[b][i][lane];      // rare: only rows with bits
                if (n >= PRE) break;
            }
        }
        if (lane == 0) s_n = n;
    }
    __syncthreads();
    int n = s_n;
    float v0 = 0, v1 = 0, v2 = 0, v3 = 0, v4 = 0, sc = 0;
    if (tid < n) {
        int i = keep[tid];
        int pos = g_perm[b][i];
        v0 = g_box[b][pos][0]; v1 = g_box[b][pos][1];
        v2 = g_box[b][pos][2]; v3 = g_box[b][pos][3];
        v4 = g_box[b][pos][4];
        sc = g_sscore[b][i];
    }
    float* ob = out + ((long long)b * PRE + tid) * 5;
    ob[0] = v0; ob[1] = v1; ob[2] = v2; ob[3] = v3; ob[4] = v4;
    out[NB * PRE * 5 + b * PRE + tid] = sc;
}

extern "C" void kernel_launch(void* const* d_in, const int* in_sizes, int n_in,
                              void* d_out, int out_size) {
    const float* obj[4] = {0, 0, 0, 0};
    const float* dlt[4] = {0, 0, 0, 0};
    const float* anch = 0;
    const int osz[4] = {786432, 196608, 49152, 12288};
    const int dsz[4] = {4718592, 1179648, 294912, 73728};
    for (int i = 0; i < n_in; i++) {
        int s = in_sizes[i];
        const float* p = (const float*)d_in[i];
        if (s == 5222400) { anch = p; continue; }
        for (int l = 0; l < 4; l++) {
            if (s == osz[l]) obj[l] = p;
            else if (s == dsz[l]) dlt[l] = p;
        }
    }
    init_kernel<<<1, 128>>>();
    select_kernel<<<NBLK, 512>>>(obj[0], obj[1], obj[2], obj[3]);
    sortdecode_kernel<<<16, 512>>>(dlt[0], dlt[1], dlt[2], dlt[3], anch);
    merge_kernel<<<NB, 512>>>();
    mask_kernel<<<528, 256>>>();
    greedy_out_kernel<<<NB, 512>>>((float*)d_out);
}

// round 10
// speedup vs baseline: 1.3375x; 1.1604x over previous
#include <cuda_runtime.h>

#define NB 4
#define PRE 512
#define NC 2048
#define TANCH 261120
#define NBIN 4096
#define SHIFT 20
#define CANDCAP 2048
#define NBLK 264
#define NINF __int_as_float(0xff800000)

// ---------------- scratch (device globals; zero-initialized) --------------
__device__ int g_hist[16][NBIN];
__device__ int g_ccnt[16];
__device__ int g_segarr[16];
__device__ unsigned long long g_rowany[NB][32];
__device__ unsigned long long g_cand[16][CANDCAP];
__device__ float g_box[NB][NC][5];                // pos-indexed
__device__ float g_score[NB][NC];                 // pos-indexed
__device__ unsigned char g_valid[NB][NC];         // pos-indexed
__device__ float g_geom[NB][NC][16];              // pos-indexed
__device__ unsigned long long g_key[NB][NC];
__device__ int g_perm[NB][NC];                    // sorted rank -> pos
__device__ unsigned char g_svalid[NB][NC];        // sorted order
__device__ float g_sscore[NB][NC];                // sorted order
__device__ unsigned long long g_mask[NB][NC][32];

__device__ const int c_aoff[4] = {0, 196608, 245760, 258048};
__device__ const int c_segblk[4] = {48, 12, 4, 2};

__device__ __forceinline__ unsigned fflip(float f) {
    unsigned u = __float_as_uint(f);
    return (u & 0x80000000u) ? ~u : (u | 0x80000000u);
}
__device__ __forceinline__ float funflip(unsigned u) {
    return __uint_as_float((u & 0x80000000u) ? (u ^ 0x80000000u) : ~u);
}

__device__ __forceinline__ void map_block(int bx, int& b, int& lvl, int& c0, int& n) {
    b = bx / 66;
    int t = bx % 66;
    if (t < 48)      { lvl = 0; c0 = t * 4096;        n = 4096; }
    else if (t < 60) { lvl = 1; c0 = (t - 48) * 4096; n = 4096; }
    else if (t < 64) { lvl = 2; c0 = (t - 60) * 3072; n = 3072; }
    else             { lvl = 3; c0 = (t - 64) * 1536; n = 1536; }
}

__device__ __forceinline__ void hist_add(int* h, unsigned bin) {
    unsigned m = __match_any_sync(0xffffffffu, bin);
    int leader = __ffs(m) - 1;
    if ((threadIdx.x & 31) == leader) atomicAdd(&h[bin], __popc(m));
}

// ---------------- stage 0: tiny init (per-replay resets) ------------------
__global__ void init_kernel() {
    int t = threadIdx.x;
    if (t < 16) g_segarr[t] = 0;
    if (t < 128) ((unsigned long long*)g_rowany)[t] = 0ull;
}

// ------------- stage 1: hist -> seg barrier -> thresh -> collect -----------
__global__ __launch_bounds__(512) void select_kernel(const float* __restrict__ o0,
                                                     const float* __restrict__ o1,
                                                     const float* __restrict__ o2,
                                                     const float* __restrict__ o3) {
    __shared__ int h[NBIN];
    int tid = threadIdx.x;
    for (int i = tid; i < NBIN; i += 512) h[i] = 0;
    __syncthreads();
    int b, lvl, c0, n;
    map_block(blockIdx.x, b, lvl, c0, n);
    const float* base = lvl == 0 ? o0 : lvl == 1 ? o1 : lvl == 2 ? o2 : o3;
    int H = 256 >> lvl, HW = H * H;
    int NL = 3 * HW;
    int seg = b * 4 + lvl;
    const float4* p4 = (const float4*)(base + (long long)b * NL + c0);
    int n4 = n >> 2;

    for (int m = tid; m < n4; m += 512) {
        float4 v = p4[m];
        hist_add(h, fflip(v.x) >> SHIFT);
        hist_add(h, fflip(v.y) >> SHIFT);
        hist_add(h, fflip(v.z) >> SHIFT);
        hist_add(h, fflip(v.w) >> SHIFT);
    }
    __syncthreads();
    for (int i = tid; i < NBIN; i += 512)
        if (h[i]) atomicAdd(&g_hist[seg][i], h[i]);

    __syncthreads();
    if (tid == 0) {
        __threadfence();
        atomicAdd(&g_segarr[seg], 1);
        int need = c_segblk[lvl];
        while (atomicAdd(&g_segarr[seg], 0) < need) {}
        __threadfence();
    }
    __syncthreads();

    // hierarchical threshold search: 8 bins/thread (descending), warp sums
    __shared__ int wsum[16];
    __shared__ int s_w, s_cum;
    __shared__ unsigned s_th;
    int loc[8];
    int lsum = 0;
#pragma unroll
    for (int k = 0; k < 8; k++) {
        loc[k] = __ldcg(&g_hist[seg][NBIN - 1 - tid * 8 - k]);
        lsum += loc[k];
    }
    int lane = tid & 31, w = tid >> 5;
    {
        int wl = lsum;
#pragma unroll
        for (int off = 16; off > 0; off >>= 1)
            wl += __shfl_down_sync(0xffffffffu, wl, off);
        if (lane == 0) wsum[w] = wl;
    }
    __syncthreads();
    if (tid == 0) {
        int cum = 0, cw = 15;
        for (int q = 0; q < 16; q++) {
            if (cum + wsum[q] >= PRE) { cw = q; break; }
            cum += wsum[q];
        }
        s_w = cw; s_cum = cum;
    }
    __syncthreads();
    if (w == s_w) {
        int pre = lsum;
#pragma unroll
        for (int off = 1; off < 32; off <<= 1) {
            int v = __shfl_up_sync(0xffffffffu, pre, off);
            if (lane >= off) pre += v;
        }
        int incl = s_cum + pre;
        unsigned ball = __ballot_sync(0xffffffffu, incl >= PRE);
        int first = __ffs(ball) - 1;
        if (lane == first) {
            int c2 = incl - lsum;
            unsigned th = 0;
#pragma unroll
            for (int k = 0; k < 8; k++) {
                c2 += loc[k];
                if (c2 >= PRE) { th = (unsigned)(NBIN - 1 - tid * 8 - k); break; }
            }
            s_th = th;
        }
    }
    __syncthreads();
    unsigned th = s_th;

    for (int m = tid; m < n4; m += 512) {
        float4 v = p4[m];
        float vals[4] = {v.x, v.y, v.z, v.w};
#pragma unroll
        for (int s = 0; s < 4; s++) {
            unsigned u = fflip(vals[s]);
            if ((u >> SHIFT) >= th) {
                int gm = c0 + m * 4 + s;
                int idx = (gm % HW) * 3 + gm / HW;   // (y*W+x)*A + a order
                int pos = atomicAdd(&g_ccnt[seg], 1);
                if (pos < CANDCAP)
                    g_cand[seg][pos] = (((unsigned long long)u) << 32) | (unsigned)(~idx);
            }
        }
    }
}

// ------- stage 2: per-segment sort -> exact top-512 -> decode + geometry ---
__global__ __launch_bounds__(512) void sortdecode_kernel(const float* __restrict__ d0,
                                                         const float* __restrict__ d1,
                                                         const float* __restrict__ d2,
                                                         const float* __restrict__ d3,
                                                         const float* __restrict__ anchors) {
    int seg = blockIdx.x;
    int sb = seg >> 2, slvl = seg & 3;
    __shared__ unsigned long long sk[CANDCAP];
    __shared__ int wtot[16], woff[16];
    __shared__ int s_tot;
    int tid = threadIdx.x;
    int cnt = g_ccnt[seg];
    if (cnt > CANDCAP) cnt = CANDCAP;
    int M = (cnt <= 1024) ? 1024 : CANDCAP;
    for (int i = tid; i < M; i += 512)
        sk[i] = (i < cnt) ? g_cand[seg][i] : 0ull;
    __syncthreads();
    if (tid == 0) { g_ccnt[seg] = 0; g_segarr[seg] = 0; }
    for (int i = tid; i < NBIN; i += 512) g_hist[seg][i] = 0;
    for (int ksz = 2; ksz <= M; ksz <<= 1) {
        for (int j = ksz >> 1; j > 0; j >>= 1) {
            for (int i = tid; i < M; i += 512) {
                int l = i ^ j;
                if (l > i) {
                    unsigned long long a = sk[i], c = sk[l];
                    bool desc = ((i & ksz) == 0);
                    if (desc ? (a < c) : (a > c)) { sk[i] = c; sk[l] = a; }
                }
            }
            __syncthreads();
        }
    }
    unsigned long long kk = sk[tid];
    float val = funflip((unsigned)(kk >> 32));
    int li = (int)(~(unsigned)(kk & 0xFFFFFFFFull));
    int sH = 256 >> slvl, sHW = sH * sH;
    int a = li % 3, cell = li / 3;
    int x = cell % sH, y = cell / sH;
    const float* dl = slvl == 0 ? d0 : slvl == 1 ? d1 : slvl == 2 ? d2 : d3;
    long long bi = ((long long)sb * 18 + a * 6) * sHW + (long long)y * sH + x;
    float dx = dl[bi], dy = dl[bi + sHW], dw = dl[bi + 2LL * sHW],
          dh = dl[bi + 3LL * sHW], ds = dl[bi + 4LL * sHW], dc = dl[bi + 5LL * sHW];
    int ta = c_aoff[slvl] + li;
    const float* an = anchors + ((long long)sb * TANCH + ta) * 5;
    float ax = an[0], ay = an[1], aw = an[2], ah = an[3], aa = an[4];
    const float LOGM = 4.135166556742356f;
    dw = fminf(dw, LOGM);
    dh = fminf(dh, LOGM);
    float bw = aw * expf(dw), bh = ah * expf(dh);
    float bcx = ax + dx * aw, bcy = ay + dy * ah;
    float ang = aa + atan2f(ds, dc);
    float sc = 0.5f + 0.5f * tanhf(0.5f * val);       // XLA logistic form
    bool vd = (bw >= 1e-3f) && (bh >= 1e-3f) && (sc >= 0.0f);

    // stable compaction: valids to front, invalids to tail
    unsigned bal = __ballot_sync(0xffffffffu, vd);
    int lane = tid & 31, w = tid >> 5;
    int prew = __popc(bal & ((1u << lane) - 1u));
    if (lane == 0) wtot[w] = __popc(bal);
    __syncthreads();
    if (tid == 0) {
        int s = 0;
        for (int q = 0; q < 16; q++) { woff[q] = s; s += wtot[q]; }
        s_tot = s;
    }
    __syncthreads();
    int vbefore = woff[w] + prew;
    int rank = vd ? vbefore : (s_tot + (tid - vbefore));
    int pos = slvl * PRE + rank;

    g_box[sb][pos][0] = bcx; g_box[sb][pos][1] = bcy;
    g_box[sb][pos][2] = bw;  g_box[sb][pos][3] = bh;
    g_box[sb][pos][4] = ang;
    g_score[sb][pos] = sc;
    g_valid[sb][pos] = vd ? 1 : 0;
    unsigned u = vd ? __float_as_uint(sc) : 0u;       // score desc, pos asc tiebreak
    g_key[sb][pos] = (((unsigned long long)u) << 32) | (unsigned)(2047 - pos);

    {
        float off = 8192.0f * (float)slvl;
        float cx = bcx + off, cy = bcy + off;
        float ca = cosf(ang), sa = sinf(ang);
        float hw = 0.5f * bw, hh = 0.5f * bh;
        float dxs[4] = {hw, -hw, -hw, hw};
        float dys[4] = {hh, hh, -hh, -hh};
        float xmn = 1e30f, xmx = -1e30f, ymn = 1e30f, ymx = -1e30f;
        float* gp = &g_geom[sb][pos][0];
#pragma unroll
        for (int c = 0; c < 4; c++) {
            float xx = cx + dxs[c] * ca - dys[c] * sa;
            float yy = cy + dxs[c] * sa + dys[c] * ca;
            gp[2 * c] = xx;
            gp[2 * c + 1] = yy;
            xmn = fminf(xmn, xx); xmx = fmaxf(xmx, xx);
            ymn = fminf(ymn, yy); ymx = fmaxf(ymx, yy);
        }
        gp[8] = bw * bh;
        gp[9] = cx;
        gp[10] = cy;
        gp[11] = 0.5f * sqrtf(bw * bw + bh * bh);
        gp[12] = xmn;
        gp[13] = xmx;
        gp[14] = ymn;
        gp[15] = ymx;
    }
}

// -------- stage 3: rank-scatter merge (lockstep binary searches) -----------
// rank(elem i of run L) = i + sum_{M != L} |{e in R_M : e > key}|.
// Keys unique (pos embedded) => exact permutation, identical to merge order.
__global__ __launch_bounds__(512) void merge_kernel() {
    int b = blockIdx.x;
    __shared__ unsigned long long sk[NC];
    int tid = threadIdx.x;
    for (int i = tid; i < NC; i += 512) sk[i] = g_key[b][i];
    __syncthreads();

    unsigned long long key[4];
#pragma unroll
    for (int L = 0; L < 4; L++) key[L] = sk[L * 512 + tid];

    // 12 lockstep descending-count binary searches (3 per element)
    int lo[4][3];
#pragma unroll
    for (int L = 0; L < 4; L++)
#pragma unroll
        for (int q = 0; q < 3; q++) lo[L][q] = 0;
#pragma unroll
    for (int step = 256; step > 0; step >>= 1) {
#pragma unroll
        for (int L = 0; L < 4; L++) {
#pragma unroll
            for (int q = 0; q < 3; q++) {
                int M = q + (q >= L ? 1 : 0);
                if (sk[M * 512 + lo[L][q] + step - 1] > key[L]) lo[L][q] += step;
            }
        }
    }
#pragma unroll
    for (int L = 0; L < 4; L++) {
        int rank = tid;
#pragma unroll
        for (int q = 0; q < 3; q++) {
            int M = q + (q >= L ? 1 : 0);
            int c = lo[L][q];
            if (sk[M * 512 + c] > key[L]) c++;       // final refinement step
            rank += c;
        }
        int pos = 2047 - (int)(unsigned)(key[L] & 0xFFFFFFFFull);
        unsigned mu = (unsigned)(key[L] >> 32);
        g_perm[b][rank] = pos;
        g_svalid[b][rank] = mu != 0u ? 1 : 0;
        g_sscore[b][rank] = mu != 0u ? __uint_as_float(mu) : NINF;
    }
}

// ---------------- stage 4: rotated IoU suppression bitmask -----------------
__device__ float inter_area(float4 pA, float4 pB, float4 qA, float4 qB) {
    float px[8], py[8], ox[8], oy[8];
    px[0] = pA.x; py[0] = pA.y; px[1] = pA.z; py[1] = pA.w;
    px[2] = pB.x; py[2] = pB.y; px[3] = pB.z; py[3] = pB.w;
    float qx[4] = {qA.x, qA.z, qB.x, qB.z};
    float qy[4] = {qA.y, qA.w, qB.y, qB.w};
    int cnt = 4;
#pragma unroll
    for (int kk = 0; kk < 4; kk++) {
        float p1x = qx[kk], p1y = qy[kk];
        int k2 = (kk + 1) & 3;
        float ex = qx[k2] - p1x, ey = qy[k2] - p1y;
        int oc = 0;
        float d0 = ex * (py[0] - p1y) - ey * (px[0] - p1x);
        float dc = d0;
        for (int i = 0; i < cnt; i++) {
            int nx = (i + 1 < cnt) ? i + 1 : 0;
            float dn = (i + 1 < cnt) ? (ex * (py[i + 1] - p1y) - ey * (px[i + 1] - p1x)) : d0;
            bool ci = dc >= 0.f, ni = dn >= 0.f;
            if (ci) { ox[oc] = px[i]; oy[oc] = py[i]; oc++; }
            if (ci != ni) {
                float den = dc - dn;
                float tt = dc / ((den == 0.f) ? 1.f : den);
                ox[oc] = px[i] + tt * (px[nx] - px[i]);
                oy[oc] = py[i] + tt * (py[nx] - py[i]);
                oc++;
            }
            dc = dn;
        }
        cnt = oc;
        if (cnt == 0) break;
        for (int i = 0; i < cnt; i++) { px[i] = ox[i]; py[i] = oy[i]; }
    }
    if (cnt < 3) return 0.f;
    float s = 0.f;
    for (int i = 0; i < cnt; i++) {
        int nx = (i + 1 < cnt) ? i + 1 : 0;
        s += px[i] * py[nx] - px[nx] * py[i];
    }
    return 0.5f * fabsf(s);
}

__global__ __launch_bounds__(256) void mask_kernel() {
    int grp = threadIdx.x >> 6, lane = threadIdx.x & 63;
    int tile = blockIdx.x * 4 + grp;
    int img = tile / 528, tri = tile % 528;
    int rb = 0, rowrem = 32;
    while (tri >= rowrem) { tri -= rowrem; rowrem--; rb++; }
    int cb = rb + tri;

    __shared__ float4 sg[4][64][4];
    __shared__ int sperm[4][64];
    const float4* gg = (const float4*)&g_geom[img][0][0];
    sperm[grp][lane] = g_perm[img][cb * 64 + lane];
    int prow = g_perm[img][rb * 64 + lane];
    __syncthreads();
    for (int i = lane; i < 256; i += 64) {
        int box = i >> 2, k = i & 3;
        sg[grp][box][k] = gg[sperm[grp][box] * 4 + k];
    }
    __syncthreads();

    int row = rb * 64 + lane;
    float4 rA = gg[prow * 4 + 0];
    float4 rB = gg[prow * 4 + 1];
    float4 rC = gg[prow * 4 + 2];
    float4 rD = gg[prow * 4 + 3];

    unsigned long long surv = 0;
#pragma unroll 4
    for (int j = 0; j < 64; j++) {
        float4 cC = sg[grp][j][2];
        float ddx = rC.y - cC.y, ddy = rC.z - cC.z;
        float rr = rC.w + cC.w;
        float mn = fminf(rC.x, cC.x), mx = fmaxf(rC.x, cC.x);
        bool ok = (ddx * ddx + ddy * ddy < rr * rr) && (mn > 0.7f * mx);
        surv |= ((unsigned long long)ok) << j;
    }
    if (cb == rb) surv &= (lane < 63) ? (~0ull << (lane + 1)) : 0ull;

    unsigned long long bits = 0;
    while (surv) {
        int j = __ffsll((long long)surv) - 1;
        surv &= surv - 1;
        float4 cC = sg[grp][j][2];
        float4 cD = sg[grp][j][3];
        float S = rC.x + cC.x;
        float xl = fmaxf(rD.x, cD.x), xr = fminf(rD.y, cD.y);
        float yl = fmaxf(rD.z, cD.z), yr = fminf(rD.w, cD.w);
        float ub = fmaxf(xr - xl, 0.f) * fmaxf(yr - yl, 0.f);
        if (ub * 1.7f < S * 0.6993f) continue;
        float inter = inter_area(rA, rB, sg[grp][j][0], sg[grp][j][1]);
        float iou = inter / (S - inter + 1e-7f);
        if (iou > 0.7f) bits |= (1ull << j);
    }
    g_mask[img][row][cb] = bits;
    if (bits)
        atomicOr(&g_rowany[img][row >> 6], 1ull << (row & 63));
}

// ---------- stage 5: chunked greedy scan + padded output -------------------
__global__ __launch_bounds__(512) void greedy_out_kernel(float* __restrict__ out) {
    int b = blockIdx.x;
    int tid = threadIdx.x;
    __shared__ int keep[PRE];
    __shared__ int s_n;
    if (tid < 32) {
        int lane = tid;
        unsigned long long remv = 0;
        const unsigned long long* vp = (const unsigned long long*)&g_svalid[b][lane * 64];
#pragma unroll
        for (int q = 0; q < 8; q++) {
            unsigned long long w8 = vp[q];
#pragma unroll
            for (int kk = 0; kk < 8; kk++)
                if (((w8 >> (kk * 8)) & 0xffull) == 0ull)
                    remv |= (1ull << (q * 8 + kk));
        }
        unsigned long long ra = g_rowany[b][lane];
        int n = 0;
        for (int c = 0; c < 32 && n < PRE; c++) {
            unsigned long long w = __shfl_sync(0xffffffffu, remv, c);
            unsigned long long raw = __shfl_sync(0xffffffffu, ra, c);
            for (int k = 0; k < 64; k++) {
                if (!((w >> k) & 1ull)) {
                    int i = c * 64 + k;
                    if (lane == 0) keep[n] = i;
                    n++;
                    if ((raw >> k) & 1ull) {          // rare: row has bits
                        remv |= g_mask[b][i][lane];
                        w = __shfl_sync(0xffffffffu, remv, c);
                    }
                    if (n >= PRE) break;
                }
            }
        }
        if (lane == 0) s_n = n;
    }
    __syncthreads();
    int n = s_n;
    float v0 = 0, v1 = 0, v2 = 0, v3 = 0, v4 = 0, sc = 0;
    if (tid < n) {
        int i = keep[tid];
        int pos = g_perm[b][i];
        v0 = g_box[b][pos][0]; v1 = g_box[b][pos][1];
        v2 = g_box[b][pos][2]; v3 = g_box[b][pos][3];
        v4 = g_box[b][pos][4];
        sc = g_sscore[b][i];
    }
    float* ob = out + ((long long)b * PRE + tid) * 5;
    ob[0] = v0; ob[1] = v1; ob[2] = v2; ob[3] = v3; ob[4] = v4;
    out[NB * PRE * 5 + b * PRE + tid] = sc;
}

extern "C" void kernel_launch(void* const* d_in, const int* in_sizes, int n_in,
                              void* d_out, int out_size) {
    const float* obj[4] = {0, 0, 0, 0};
    const float* dlt[4] = {0, 0, 0, 0};
    const float* anch = 0;
    const int osz[4] = {786432, 196608, 49152, 12288};
    const int dsz[4] = {4718592, 1179648, 294912, 73728};
    for (int i = 0; i < n_in; i++) {
        int s = in_sizes[i];
        const float* p = (const float*)d_in[i];
        if (s == 5222400) { anch = p; continue; }
        for (int l = 0; l < 4; l++) {
            if (s == osz[l]) obj[l] = p;
            else if (s == dsz[l]) dlt[l] = p;
        }
    }
    init_kernel<<<1, 128>>>();
    select_kernel<<<NBLK, 512>>>(obj[0], obj[1], obj[2], obj[3]);
    sortdecode_kernel<<<16, 512>>>(dlt[0], dlt[1], dlt[2], dlt[3], anch);
    merge_kernel<<<NB, 512>>>();
    mask_kernel<<<528, 256>>>();
    greedy_out_kernel<<<NB, 512>>>((float*)d_out);
}

// round 11
// speedup vs baseline: 1.3579x; 1.0152x over previous
#include <cuda_runtime.h>

#define NB 4
#define PRE 512
#define NC 2048
#define TANCH 261120
#define NBIN 4096
#define SHIFT 20
#define CANDCAP 2048
#define NBLK 264
#define NINF __int_as_float(0xff800000)

// ---------------- scratch (device globals; zero-initialized) --------------
__device__ int g_hist[16][NBIN];
__device__ int g_ccnt[16];
__device__ int g_segarr[16];
__device__ int g_imgarr[NB];
__device__ unsigned long long g_rowany[NB][32];
__device__ unsigned long long g_cand[16][CANDCAP];
__device__ float g_box[NB][NC][5];                // pos-indexed
__device__ float g_score[NB][NC];                 // pos-indexed
__device__ unsigned char g_valid[NB][NC];         // pos-indexed
__device__ float g_geom[NB][NC][16];              // pos-indexed
__device__ unsigned long long g_key[NB][NC];
__device__ int g_perm[NB][NC];                    // sorted rank -> pos
__device__ unsigned char g_svalid[NB][NC];        // sorted order
__device__ float g_sscore[NB][NC];                // sorted order
__device__ unsigned long long g_mask[NB][NC][32];

__device__ const int c_aoff[4] = {0, 196608, 245760, 258048};
__device__ const int c_segblk[4] = {48, 12, 4, 2};

__device__ __forceinline__ unsigned fflip(float f) {
    unsigned u = __float_as_uint(f);
    return (u & 0x80000000u) ? ~u : (u | 0x80000000u);
}
__device__ __forceinline__ float funflip(unsigned u) {
    return __uint_as_float((u & 0x80000000u) ? (u ^ 0x80000000u) : ~u);
}

__device__ __forceinline__ void map_block(int bx, int& b, int& lvl, int& c0, int& n) {
    b = bx / 66;
    int t = bx % 66;
    if (t < 48)      { lvl = 0; c0 = t * 4096;        n = 4096; }
    else if (t < 60) { lvl = 1; c0 = (t - 48) * 4096; n = 4096; }
    else if (t < 64) { lvl = 2; c0 = (t - 60) * 3072; n = 3072; }
    else             { lvl = 3; c0 = (t - 64) * 1536; n = 1536; }
}

__device__ __forceinline__ void hist_add(int* h, unsigned bin) {
    unsigned m = __match_any_sync(0xffffffffu, bin);
    int leader = __ffs(m) - 1;
    if ((threadIdx.x & 31) == leader) atomicAdd(&h[bin], __popc(m));
}

// ------------- stage 1: hist -> seg barrier -> thresh -> collect -----------
__global__ __launch_bounds__(512) void select_kernel(const float* __restrict__ o0,
                                                     const float* __restrict__ o1,
                                                     const float* __restrict__ o2,
                                                     const float* __restrict__ o3) {
    __shared__ int h[NBIN];
    int tid = threadIdx.x;
    for (int i = tid; i < NBIN; i += 512) h[i] = 0;
    __syncthreads();
    int b, lvl, c0, n;
    map_block(blockIdx.x, b, lvl, c0, n);
    const float* base = lvl == 0 ? o0 : lvl == 1 ? o1 : lvl == 2 ? o2 : o3;
    int H = 256 >> lvl, HW = H * H;
    int NL = 3 * HW;
    int seg = b * 4 + lvl;
    const float4* p4 = (const float4*)(base + (long long)b * NL + c0);
    int n4 = n >> 2;

    for (int m = tid; m < n4; m += 512) {
        float4 v = p4[m];
        hist_add(h, fflip(v.x) >> SHIFT);
        hist_add(h, fflip(v.y) >> SHIFT);
        hist_add(h, fflip(v.z) >> SHIFT);
        hist_add(h, fflip(v.w) >> SHIFT);
    }
    __syncthreads();
    for (int i = tid; i < NBIN; i += 512)
        if (h[i]) atomicAdd(&g_hist[seg][i], h[i]);

    __syncthreads();
    if (tid == 0) {
        __threadfence();
        atomicAdd(&g_segarr[seg], 1);
        int need = c_segblk[lvl];
        while (atomicAdd(&g_segarr[seg], 0) < need) {}
        __threadfence();
    }
    __syncthreads();

    // hierarchical threshold search: 8 bins/thread (descending), warp sums
    __shared__ int wsum[16];
    __shared__ int s_w, s_cum;
    __shared__ unsigned s_th;
    int loc[8];
    int lsum = 0;
#pragma unroll
    for (int k = 0; k < 8; k++) {
        loc[k] = __ldcg(&g_hist[seg][NBIN - 1 - tid * 8 - k]);
        lsum += loc[k];
    }
    int lane = tid & 31, w = tid >> 5;
    {
        int wl = lsum;
#pragma unroll
        for (int off = 16; off > 0; off >>= 1)
            wl += __shfl_down_sync(0xffffffffu, wl, off);
        if (lane == 0) wsum[w] = wl;
    }
    __syncthreads();
    if (tid == 0) {
        int cum = 0, cw = 15;
        for (int q = 0; q < 16; q++) {
            if (cum + wsum[q] >= PRE) { cw = q; break; }
            cum += wsum[q];
        }
        s_w = cw; s_cum = cum;
    }
    __syncthreads();
    if (w == s_w) {
        int pre = lsum;
#pragma unroll
        for (int off = 1; off < 32; off <<= 1) {
            int v = __shfl_up_sync(0xffffffffu, pre, off);
            if (lane >= off) pre += v;
        }
        int incl = s_cum + pre;
        unsigned ball = __ballot_sync(0xffffffffu, incl >= PRE);
        int first = __ffs(ball) - 1;
        if (lane == first) {
            int c2 = incl - lsum;
            unsigned th = 0;
#pragma unroll
            for (int k = 0; k < 8; k++) {
                c2 += loc[k];
                if (c2 >= PRE) { th = (unsigned)(NBIN - 1 - tid * 8 - k); break; }
            }
            s_th = th;
        }
    }
    __syncthreads();
    unsigned th = s_th;

    for (int m = tid; m < n4; m += 512) {
        float4 v = p4[m];
        float vals[4] = {v.x, v.y, v.z, v.w};
#pragma unroll
        for (int s = 0; s < 4; s++) {
            unsigned u = fflip(vals[s]);
            if ((u >> SHIFT) >= th) {
                int gm = c0 + m * 4 + s;
                int idx = (gm % HW) * 3 + gm / HW;   // (y*W+x)*A + a order
                int pos = atomicAdd(&g_ccnt[seg], 1);
                if (pos < CANDCAP)
                    g_cand[seg][pos] = (((unsigned long long)u) << 32) | (unsigned)(~idx);
            }
        }
    }
}

// -- stage 2: sort -> top-512 -> decode + geometry; slvl==0 block merges ----
__global__ __launch_bounds__(512) void sortdecode_kernel(const float* __restrict__ d0,
                                                         const float* __restrict__ d1,
                                                         const float* __restrict__ d2,
                                                         const float* __restrict__ d3,
                                                         const float* __restrict__ anchors) {
    int seg = blockIdx.x;
    int sb = seg >> 2, slvl = seg & 3;
    __shared__ unsigned long long sk[CANDCAP];
    __shared__ int wtot[16], woff[16];
    __shared__ int s_tot;
    int tid = threadIdx.x;
    int cnt = g_ccnt[seg];
    if (cnt > CANDCAP) cnt = CANDCAP;
    int M = (cnt <= 1024) ? 1024 : CANDCAP;
    for (int i = tid; i < M; i += 512)
        sk[i] = (i < cnt) ? g_cand[seg][i] : 0ull;
    __syncthreads();
    if (tid == 0) { g_ccnt[seg] = 0; g_segarr[seg] = 0; }
    for (int i = tid; i < NBIN; i += 512) g_hist[seg][i] = 0;
    for (int ksz = 2; ksz <= M; ksz <<= 1) {
        for (int j = ksz >> 1; j > 0; j >>= 1) {
            for (int i = tid; i < M; i += 512) {
                int l = i ^ j;
                if (l > i) {
                    unsigned long long a = sk[i], c = sk[l];
                    bool desc = ((i & ksz) == 0);
                    if (desc ? (a < c) : (a > c)) { sk[i] = c; sk[l] = a; }
                }
            }
            __syncthreads();
        }
    }
    unsigned long long kk = sk[tid];
    float val = funflip((unsigned)(kk >> 32));
    int li = (int)(~(unsigned)(kk & 0xFFFFFFFFull));
    int sH = 256 >> slvl, sHW = sH * sH;
    int a = li % 3, cell = li / 3;
    int x = cell % sH, y = cell / sH;
    const float* dl = slvl == 0 ? d0 : slvl == 1 ? d1 : slvl == 2 ? d2 : d3;
    long long bi = ((long long)sb * 18 + a * 6) * sHW + (long long)y * sH + x;
    float dx = dl[bi], dy = dl[bi + sHW], dw = dl[bi + 2LL * sHW],
          dh = dl[bi + 3LL * sHW], ds = dl[bi + 4LL * sHW], dc = dl[bi + 5LL * sHW];
    int ta = c_aoff[slvl] + li;
    const float* an = anchors + ((long long)sb * TANCH + ta) * 5;
    float ax = an[0], ay = an[1], aw = an[2], ah = an[3], aa = an[4];
    const float LOGM = 4.135166556742356f;
    dw = fminf(dw, LOGM);
    dh = fminf(dh, LOGM);
    float bw = aw * expf(dw), bh = ah * expf(dh);
    float bcx = ax + dx * aw, bcy = ay + dy * ah;
    float ang = aa + atan2f(ds, dc);
    float sc = 0.5f + 0.5f * tanhf(0.5f * val);       // XLA logistic form
    bool vd = (bw >= 1e-3f) && (bh >= 1e-3f) && (sc >= 0.0f);

    // stable compaction: valids to front, invalids to tail
    unsigned bal = __ballot_sync(0xffffffffu, vd);
    int lane = tid & 31, w = tid >> 5;
    int prew = __popc(bal & ((1u << lane) - 1u));
    if (lane == 0) wtot[w] = __popc(bal);
    __syncthreads();
    if (tid == 0) {
        int s = 0;
        for (int q = 0; q < 16; q++) { woff[q] = s; s += wtot[q]; }
        s_tot = s;
    }
    __syncthreads();
    int vbefore = woff[w] + prew;
    int rank = vd ? vbefore : (s_tot + (tid - vbefore));
    int pos = slvl * PRE + rank;

    g_box[sb][pos][0] = bcx; g_box[sb][pos][1] = bcy;
    g_box[sb][pos][2] = bw;  g_box[sb][pos][3] = bh;
    g_box[sb][pos][4] = ang;
    g_score[sb][pos] = sc;
    g_valid[sb][pos] = vd ? 1 : 0;
    unsigned u = vd ? __float_as_uint(sc) : 0u;       // score desc, pos asc tiebreak
    g_key[sb][pos] = (((unsigned long long)u) << 32) | (unsigned)(2047 - pos);

    {
        float off = 8192.0f * (float)slvl;
        float cx = bcx + off, cy = bcy + off;
        float ca = cosf(ang), sa = sinf(ang);
        float hw = 0.5f * bw, hh = 0.5f * bh;
        float dxs[4] = {hw, -hw, -hw, hw};
        float dys[4] = {hh, hh, -hh, -hh};
        float xmn = 1e30f, xmx = -1e30f, ymn = 1e30f, ymx = -1e30f;
        float* gp = &g_geom[sb][pos][0];
#pragma unroll
        for (int c = 0; c < 4; c++) {
            float xx = cx + dxs[c] * ca - dys[c] * sa;
            float yy = cy + dxs[c] * sa + dys[c] * ca;
            gp[2 * c] = xx;
            gp[2 * c + 1] = yy;
            xmn = fminf(xmn, xx); xmx = fmaxf(xmx, xx);
            ymn = fminf(ymn, yy); ymx = fmaxf(ymx, yy);
        }
        gp[8] = bw * bh;
        gp[9] = cx;
        gp[10] = cy;
        gp[11] = 0.5f * sqrtf(bw * bw + bh * bh);
        gp[12] = xmn;
        gp[13] = xmx;
        gp[14] = ymn;
        gp[15] = ymx;
    }

    // ---- publish this segment's run, then slvl==0 block merges the image --
    __threadfence();                       // all threads: make writes visible
    __syncthreads();
    if (tid == 0) atomicAdd(&g_imgarr[sb], 1);
    if (slvl != 0) return;
    if (tid == 0) {
        while (atomicAdd(&g_imgarr[sb], 0) < 4) {}
        g_imgarr[sb] = 0;                  // single writer; reset for next replay
        __threadfence();
    }
    __syncthreads();
    // reset rowany for this image (consumed by mask/greedy of THIS replay)
    if (tid < 32) g_rowany[sb][tid] = 0ull;
    // reload all 4 runs (L2-fresh)
    for (int i = tid; i < NC; i += 512) sk[i] = __ldcg(&g_key[sb][i]);
    __syncthreads();

    // rank-scatter merge: 12 lockstep descending-count binary searches
    unsigned long long mkey[4];
#pragma unroll
    for (int L = 0; L < 4; L++) mkey[L] = sk[L * 512 + tid];
    int lo[4][3];
#pragma unroll
    for (int L = 0; L < 4; L++)
#pragma unroll
        for (int q = 0; q < 3; q++) lo[L][q] = 0;
#pragma unroll
    for (int step = 256; step > 0; step >>= 1) {
#pragma unroll
        for (int L = 0; L < 4; L++) {
#pragma unroll
            for (int q = 0; q < 3; q++) {
                int Mi = q + (q >= L ? 1 : 0);
                if (sk[Mi * 512 + lo[L][q] + step - 1] > mkey[L]) lo[L][q] += step;
            }
        }
    }
#pragma unroll
    for (int L = 0; L < 4; L++) {
        int mrank = tid;
#pragma unroll
        for (int q = 0; q < 3; q++) {
            int Mi = q + (q >= L ? 1 : 0);
            int c = lo[L][q];
            if (sk[Mi * 512 + c] > mkey[L]) c++;
            mrank += c;
        }
        int mpos = 2047 - (int)(unsigned)(mkey[L] & 0xFFFFFFFFull);
        unsigned mu = (unsigned)(mkey[L] >> 32);
        g_perm[sb][mrank] = mpos;
        g_svalid[sb][mrank] = mu != 0u ? 1 : 0;
        g_sscore[sb][mrank] = mu != 0u ? __uint_as_float(mu) : NINF;
    }
}

// ---------------- stage 3: rotated IoU suppression bitmask -----------------
__device__ float inter_area(float4 pA, float4 pB, float4 qA, float4 qB) {
    float px[8], py[8], ox[8], oy[8];
    px[0] = pA.x; py[0] = pA.y; px[1] = pA.z; py[1] = pA.w;
    px[2] = pB.x; py[2] = pB.y; px[3] = pB.z; py[3] = pB.w;
    float qx[4] = {qA.x, qA.z, qB.x, qB.z};
    float qy[4] = {qA.y, qA.w, qB.y, qB.w};
    int cnt = 4;
#pragma unroll
    for (int kk = 0; kk < 4; kk++) {
        float p1x = qx[kk], p1y = qy[kk];
        int k2 = (kk + 1) & 3;
        float ex = qx[k2] - p1x, ey = qy[k2] - p1y;
        int oc = 0;
        float d0 = ex * (py[0] - p1y) - ey * (px[0] - p1x);
        float dc = d0;
        for (int i = 0; i < cnt; i++) {
            int nx = (i + 1 < cnt) ? i + 1 : 0;
            float dn = (i + 1 < cnt) ? (ex * (py[i + 1] - p1y) - ey * (px[i + 1] - p1x)) : d0;
            bool ci = dc >= 0.f, ni = dn >= 0.f;
            if (ci) { ox[oc] = px[i]; oy[oc] = py[i]; oc++; }
            if (ci != ni) {
                float den = dc - dn;
                float tt = dc / ((den == 0.f) ? 1.f : den);
                ox[oc] = px[i] + tt * (px[nx] - px[i]);
                oy[oc] = py[i] + tt * (py[nx] - py[i]);
                oc++;
            }
            dc = dn;
        }
        cnt = oc;
        if (cnt == 0) break;
        for (int i = 0; i < cnt; i++) { px[i] = ox[i]; py[i] = oy[i]; }
    }
    if (cnt < 3) return 0.f;
    float s = 0.f;
    for (int i = 0; i < cnt; i++) {
        int nx = (i + 1 < cnt) ? i + 1 : 0;
        s += px[i] * py[nx] - px[nx] * py[i];
    }
    return 0.5f * fabsf(s);
}

__global__ __launch_bounds__(256) void mask_kernel() {
    int grp = threadIdx.x >> 6, lane = threadIdx.x & 63;
    int tile = blockIdx.x * 4 + grp;
    int img = tile / 528, tri = tile % 528;
    int rb = 0, rowrem = 32;
    while (tri >= rowrem) { tri -= rowrem; rowrem--; rb++; }
    int cb = rb + tri;

    __shared__ float4 sg[4][64][4];
    __shared__ int sperm[4][64];
    const float4* gg = (const float4*)&g_geom[img][0][0];
    sperm[grp][lane] = g_perm[img][cb * 64 + lane];
    int prow = g_perm[img][rb * 64 + lane];
    __syncthreads();
    for (int i = lane; i < 256; i += 64) {
        int box = i >> 2, k = i & 3;
        sg[grp][box][k] = gg[sperm[grp][box] * 4 + k];
    }
    __syncthreads();

    int row = rb * 64 + lane;
    float4 rA = gg[prow * 4 + 0];
    float4 rB = gg[prow * 4 + 1];
    float4 rC = gg[prow * 4 + 2];
    float4 rD = gg[prow * 4 + 3];

    unsigned long long surv = 0;
#pragma unroll 4
    for (int j = 0; j < 64; j++) {
        float4 cC = sg[grp][j][2];
        float ddx = rC.y - cC.y, ddy = rC.z - cC.z;
        float rr = rC.w + cC.w;
        float mn = fminf(rC.x, cC.x), mx = fmaxf(rC.x, cC.x);
        bool ok = (ddx * ddx + ddy * ddy < rr * rr) && (mn > 0.7f * mx);
        surv |= ((unsigned long long)ok) << j;
    }
    if (cb == rb) surv &= (lane < 63) ? (~0ull << (lane + 1)) : 0ull;

    unsigned long long bits = 0;
    while (surv) {
        int j = __ffsll((long long)surv) - 1;
        surv &= surv - 1;
        float4 cC = sg[grp][j][2];
        float4 cD = sg[grp][j][3];
        float S = rC.x + cC.x;
        float xl = fmaxf(rD.x, cD.x), xr = fminf(rD.y, cD.y);
        float yl = fmaxf(rD.z, cD.z), yr = fminf(rD.w, cD.w);
        float ub = fmaxf(xr - xl, 0.f) * fmaxf(yr - yl, 0.f);
        if (ub * 1.7f < S * 0.6993f) continue;
        float inter = inter_area(rA, rB, sg[grp][j][0], sg[grp][j][1]);
        float iou = inter / (S - inter + 1e-7f);
        if (iou > 0.7f) bits |= (1ull << j);
    }
    g_mask[img][row][cb] = bits;
    if (bits)
        atomicOr(&g_rowany[img][row >> 6], 1ull << (row & 63));
}

// ---------- stage 4: chunked greedy scan + padded output -------------------
__global__ __launch_bounds__(512) void greedy_out_kernel(float* __restrict__ out) {
    int b = blockIdx.x;
    int tid = threadIdx.x;
    __shared__ int keep[PRE];
    __shared__ int s_n;
    if (tid < 32) {
        int lane = tid;
        unsigned long long remv = 0;
        const unsigned long long* vp = (const unsigned long long*)&g_svalid[b][lane * 64];
#pragma unroll
        for (int q = 0; q < 8; q++) {
            unsigned long long w8 = vp[q];
#pragma unroll
            for (int kk = 0; kk < 8; kk++)
                if (((w8 >> (kk * 8)) & 0xffull) == 0ull)
                    remv |= (1ull << (q * 8 + kk));
        }
        unsigned long long ra = g_rowany[b][lane];
        int n = 0;
        for (int c = 0; c < 32 && n < PRE; c++) {
            unsigned long long w = __shfl_sync(0xffffffffu, remv, c);
            unsigned long long raw = __shfl_sync(0xffffffffu, ra, c);
            for (int k = 0; k < 64; k++) {
                if (!((w >> k) & 1ull)) {
                    int i = c * 64 + k;
                    if (lane == 0) keep[n] = i;
                    n++;
                    if ((raw >> k) & 1ull) {
                        remv |= g_mask[b][i][lane];
                        w = __shfl_sync(0xffffffffu, remv, c);
                    }
                    if (n >= PRE) break;
                }
            }
        }
        if (lane == 0) s_n = n;
    }
    __syncthreads();
    int n = s_n;
    float v0 = 0, v1 = 0, v2 = 0, v3 = 0, v4 = 0, sc = 0;
    if (tid < n) {
        int i = keep[tid];
        int pos = g_perm[b][i];
        v0 = g_box[b][pos][0]; v1 = g_box[b][pos][1];
        v2 = g_box[b][pos][2]; v3 = g_box[b][pos][3];
        v4 = g_box[b][pos][4];
        sc = g_sscore[b][i];
    }
    float* ob = out + ((long long)b * PRE + tid) * 5;
    ob[0] = v0; ob[1] = v1; ob[2] = v2; ob[3] = v3; ob[4] = v4;
    out[NB * PRE * 5 + b * PRE + tid] = sc;
}

extern "C" void kernel_launch(void* const* d_in, const int* in_sizes, int n_in,
                              void* d_out, int out_size) {
    const float* obj[4] = {0, 0, 0, 0};
    const float* dlt[4] = {0, 0, 0, 0};
    const float* anch = 0;
    const int osz[4] = {786432, 196608, 49152, 12288};
    const int dsz[4] = {4718592, 1179648, 294912, 73728};
    for (int i = 0; i < n_in; i++) {
        int s = in_sizes[i];
        const float* p = (const float*)d_in[i];
        if (s == 5222400) { anch = p; continue; }
        for (int l = 0; l < 4; l++) {
            if (s == osz[l]) obj[l] = p;
            else if (s == dsz[l]) dlt[l] = p;
        }
    }
    select_kernel<<<NBLK, 512>>>(obj[0], obj[1], obj[2], obj[3]);
    sortdecode_kernel<<<16, 512>>>(dlt[0], dlt[1], dlt[2], dlt[3], anch);
    mask_kernel<<<528, 256>>>();
    greedy_out_kernel<<<NB, 512>>>((float*)d_out);
}

// round 12
// speedup vs baseline: 1.9743x; 1.4539x over previous
#include <cuda_runtime.h>

#define NB 4
#define PRE 512
#define NC 2048
#define TANCH 261120
#define NBIN 4096
#define SHIFT 20
#define CANDCAP 2048
#define NBLK 264
#define SMAX 160
#define NINF __int_as_float(0xff800000)

// ---------------- scratch (device globals; zero-initialized) --------------
__device__ int g_hist[16][NBIN];
__device__ int g_ccnt[16];
__device__ int g_segarr[16];
__device__ int g_imgarr[NB];
__device__ unsigned long long g_rowany[NB][32];
__device__ unsigned long long g_cand[16][CANDCAP];
__device__ float g_box[NB][NC][5];                // pos-indexed
__device__ float g_score[NB][NC];                 // pos-indexed
__device__ unsigned char g_valid[NB][NC];         // pos-indexed
__device__ float g_geom[NB][NC][16];              // pos-indexed
__device__ unsigned long long g_key[NB][NC];
__device__ int g_perm[NB][NC];                    // sorted rank -> pos
__device__ unsigned char g_svalid[NB][NC];        // sorted order
__device__ float g_sscore[NB][NC];                // sorted order
__device__ unsigned long long g_mask[NB][NC][32];

__device__ const int c_aoff[4] = {0, 196608, 245760, 258048};
__device__ const int c_segblk[4] = {48, 12, 4, 2};

__device__ __forceinline__ unsigned fflip(float f) {
    unsigned u = __float_as_uint(f);
    return (u & 0x80000000u) ? ~u : (u | 0x80000000u);
}
__device__ __forceinline__ float funflip(unsigned u) {
    return __uint_as_float((u & 0x80000000u) ? (u ^ 0x80000000u) : ~u);
}

__device__ __forceinline__ void map_block(int bx, int& b, int& lvl, int& c0, int& n) {
    b = bx / 66;
    int t = bx % 66;
    if (t < 48)      { lvl = 0; c0 = t * 4096;        n = 4096; }
    else if (t < 60) { lvl = 1; c0 = (t - 48) * 4096; n = 4096; }
    else if (t < 64) { lvl = 2; c0 = (t - 60) * 3072; n = 3072; }
    else             { lvl = 3; c0 = (t - 64) * 1536; n = 1536; }
}

__device__ __forceinline__ void hist_add(int* h, unsigned bin) {
    unsigned m = __match_any_sync(0xffffffffu, bin);
    int leader = __ffs(m) - 1;
    if ((threadIdx.x & 31) == leader) atomicAdd(&h[bin], __popc(m));
}

// select the r-th (0-based) set bit of a 64-bit word
__device__ __forceinline__ int sel64(unsigned long long word, int r) {
    unsigned lo = (unsigned)word;
    int cl = __popc(lo);
    if (r < cl) return __fns(lo, 0, r + 1);
    return 32 + __fns((unsigned)(word >> 32), 0, r - cl + 1);
}

// ------------- stage 1: hist -> seg barrier -> thresh -> collect -----------
__global__ __launch_bounds__(512) void select_kernel(const float* __restrict__ o0,
                                                     const float* __restrict__ o1,
                                                     const float* __restrict__ o2,
                                                     const float* __restrict__ o3) {
    __shared__ int h[NBIN];
    int tid = threadIdx.x;
    for (int i = tid; i < NBIN; i += 512) h[i] = 0;
    __syncthreads();
    int b, lvl, c0, n;
    map_block(blockIdx.x, b, lvl, c0, n);
    const float* base = lvl == 0 ? o0 : lvl == 1 ? o1 : lvl == 2 ? o2 : o3;
    int H = 256 >> lvl, HW = H * H;
    int NL = 3 * HW;
    int seg = b * 4 + lvl;
    const float4* p4 = (const float4*)(base + (long long)b * NL + c0);
    int n4 = n >> 2;

    for (int m = tid; m < n4; m += 512) {
        float4 v = p4[m];
        hist_add(h, fflip(v.x) >> SHIFT);
        hist_add(h, fflip(v.y) >> SHIFT);
        hist_add(h, fflip(v.z) >> SHIFT);
        hist_add(h, fflip(v.w) >> SHIFT);
    }
    __syncthreads();
    for (int i = tid; i < NBIN; i += 512)
        if (h[i]) atomicAdd(&g_hist[seg][i], h[i]);

    __syncthreads();
    if (tid == 0) {
        __threadfence();
        atomicAdd(&g_segarr[seg], 1);
        int need = c_segblk[lvl];
        while (atomicAdd(&g_segarr[seg], 0) < need) {}
        __threadfence();
    }
    __syncthreads();

    __shared__ int wsum[16];
    __shared__ int s_w, s_cum;
    __shared__ unsigned s_th;
    int loc[8];
    int lsum = 0;
#pragma unroll
    for (int k = 0; k < 8; k++) {
        loc[k] = __ldcg(&g_hist[seg][NBIN - 1 - tid * 8 - k]);
        lsum += loc[k];
    }
    int lane = tid & 31, w = tid >> 5;
    {
        int wl = lsum;
#pragma unroll
        for (int off = 16; off > 0; off >>= 1)
            wl += __shfl_down_sync(0xffffffffu, wl, off);
        if (lane == 0) wsum[w] = wl;
    }
    __syncthreads();
    if (tid == 0) {
        int cum = 0, cw = 15;
        for (int q = 0; q < 16; q++) {
            if (cum + wsum[q] >= PRE) { cw = q; break; }
            cum += wsum[q];
        }
        s_w = cw; s_cum = cum;
    }
    __syncthreads();
    if (w == s_w) {
        int pre = lsum;
#pragma unroll
        for (int off = 1; off < 32; off <<= 1) {
            int v = __shfl_up_sync(0xffffffffu, pre, off);
            if (lane >= off) pre += v;
        }
        int incl = s_cum + pre;
        unsigned ball = __ballot_sync(0xffffffffu, incl >= PRE);
        int first = __ffs(ball) - 1;
        if (lane == first) {
            int c2 = incl - lsum;
            unsigned th = 0;
#pragma unroll
            for (int k = 0; k < 8; k++) {
                c2 += loc[k];
                if (c2 >= PRE) { th = (unsigned)(NBIN - 1 - tid * 8 - k); break; }
            }
            s_th = th;
        }
    }
    __syncthreads();
    unsigned th = s_th;

    for (int m = tid; m < n4; m += 512) {
        float4 v = p4[m];
        float vals[4] = {v.x, v.y, v.z, v.w};
#pragma unroll
        for (int s = 0; s < 4; s++) {
            unsigned u = fflip(vals[s]);
            if ((u >> SHIFT) >= th) {
                int gm = c0 + m * 4 + s;
                int idx = (gm % HW) * 3 + gm / HW;   // (y*W+x)*A + a order
                int pos = atomicAdd(&g_ccnt[seg], 1);
                if (pos < CANDCAP)
                    g_cand[seg][pos] = (((unsigned long long)u) << 32) | (unsigned)(~idx);
            }
        }
    }
}

// -- stage 2: sort -> top-512 -> decode + geometry; slvl==0 block merges ----
__global__ __launch_bounds__(512) void sortdecode_kernel(const float* __restrict__ d0,
                                                         const float* __restrict__ d1,
                                                         const float* __restrict__ d2,
                                                         const float* __restrict__ d3,
                                                         const float* __restrict__ anchors) {
    int seg = blockIdx.x;
    int sb = seg >> 2, slvl = seg & 3;
    __shared__ unsigned long long sk[CANDCAP];
    __shared__ int wtot[16], woff[16];
    __shared__ int s_tot;
    int tid = threadIdx.x;
    int cnt = g_ccnt[seg];
    if (cnt > CANDCAP) cnt = CANDCAP;
    int M = (cnt <= 1024) ? 1024 : CANDCAP;
    for (int i = tid; i < M; i += 512)
        sk[i] = (i < cnt) ? g_cand[seg][i] : 0ull;
    __syncthreads();
    if (tid == 0) { g_ccnt[seg] = 0; g_segarr[seg] = 0; }
    for (int i = tid; i < NBIN; i += 512) g_hist[seg][i] = 0;
    for (int ksz = 2; ksz <= M; ksz <<= 1) {
        for (int j = ksz >> 1; j > 0; j >>= 1) {
            for (int i = tid; i < M; i += 512) {
                int l = i ^ j;
                if (l > i) {
                    unsigned long long a = sk[i], c = sk[l];
                    bool desc = ((i & ksz) == 0);
                    if (desc ? (a < c) : (a > c)) { sk[i] = c; sk[l] = a; }
                }
            }
            __syncthreads();
        }
    }
    unsigned long long kk = sk[tid];
    float val = funflip((unsigned)(kk >> 32));
    int li = (int)(~(unsigned)(kk & 0xFFFFFFFFull));
    int sH = 256 >> slvl, sHW = sH * sH;
    int a = li % 3, cell = li / 3;
    int x = cell % sH, y = cell / sH;
    const float* dl = slvl == 0 ? d0 : slvl == 1 ? d1 : slvl == 2 ? d2 : d3;
    long long bi = ((long long)sb * 18 + a * 6) * sHW + (long long)y * sH + x;
    float dx = dl[bi], dy = dl[bi + sHW], dw = dl[bi + 2LL * sHW],
          dh = dl[bi + 3LL * sHW], ds = dl[bi + 4LL * sHW], dc = dl[bi + 5LL * sHW];
    int ta = c_aoff[slvl] + li;
    const float* an = anchors + ((long long)sb * TANCH + ta) * 5;
    float ax = an[0], ay = an[1], aw = an[2], ah = an[3], aa = an[4];
    const float LOGM = 4.135166556742356f;
    dw = fminf(dw, LOGM);
    dh = fminf(dh, LOGM);
    float bw = aw * expf(dw), bh = ah * expf(dh);
    float bcx = ax + dx * aw, bcy = ay + dy * ah;
    float ang = aa + atan2f(ds, dc);
    float sc = 0.5f + 0.5f * tanhf(0.5f * val);       // XLA logistic form
    bool vd = (bw >= 1e-3f) && (bh >= 1e-3f) && (sc >= 0.0f);

    unsigned bal = __ballot_sync(0xffffffffu, vd);
    int lane = tid & 31, w = tid >> 5;
    int prew = __popc(bal & ((1u << lane) - 1u));
    if (lane == 0) wtot[w] = __popc(bal);
    __syncthreads();
    if (tid == 0) {
        int s = 0;
        for (int q = 0; q < 16; q++) { woff[q] = s; s += wtot[q]; }
        s_tot = s;
    }
    __syncthreads();
    int vbefore = woff[w] + prew;
    int rank = vd ? vbefore : (s_tot + (tid - vbefore));
    int pos = slvl * PRE + rank;

    g_box[sb][pos][0] = bcx; g_box[sb][pos][1] = bcy;
    g_box[sb][pos][2] = bw;  g_box[sb][pos][3] = bh;
    g_box[sb][pos][4] = ang;
    g_score[sb][pos] = sc;
    g_valid[sb][pos] = vd ? 1 : 0;
    unsigned u = vd ? __float_as_uint(sc) : 0u;       // score desc, pos asc tiebreak
    g_key[sb][pos] = (((unsigned long long)u) << 32) | (unsigned)(2047 - pos);

    {
        float off = 8192.0f * (float)slvl;
        float cx = bcx + off, cy = bcy + off;
        float ca = cosf(ang), sa = sinf(ang);
        float hw = 0.5f * bw, hh = 0.5f * bh;
        float dxs[4] = {hw, -hw, -hw, hw};
        float dys[4] = {hh, hh, -hh, -hh};
        float xmn = 1e30f, xmx = -1e30f, ymn = 1e30f, ymx = -1e30f;
        float* gp = &g_geom[sb][pos][0];
#pragma unroll
        for (int c = 0; c < 4; c++) {
            float xx = cx + dxs[c] * ca - dys[c] * sa;
            float yy = cy + dxs[c] * sa + dys[c] * ca;
            gp[2 * c] = xx;
            gp[2 * c + 1] = yy;
            xmn = fminf(xmn, xx); xmx = fmaxf(xmx, xx);
            ymn = fminf(ymn, yy); ymx = fmaxf(ymx, yy);
        }
        gp[8] = bw * bh;
        gp[9] = cx;
        gp[10] = cy;
        gp[11] = 0.5f * sqrtf(bw * bw + bh * bh);
        gp[12] = xmn;
        gp[13] = xmx;
        gp[14] = ymn;
        gp[15] = ymx;
    }

    // ---- publish this segment's run, then slvl==0 block merges the image --
    __threadfence();
    __syncthreads();
    if (tid == 0) atomicAdd(&g_imgarr[sb], 1);
    if (slvl != 0) return;
    if (tid == 0) {
        while (atomicAdd(&g_imgarr[sb], 0) < 4) {}
        g_imgarr[sb] = 0;
        __threadfence();
    }
    __syncthreads();
    if (tid < 32) g_rowany[sb][tid] = 0ull;
    for (int i = tid; i < NC; i += 512) sk[i] = __ldcg(&g_key[sb][i]);
    __syncthreads();

    unsigned long long mkey[4];
#pragma unroll
    for (int L = 0; L < 4; L++) mkey[L] = sk[L * 512 + tid];
    int lo[4][3];
#pragma unroll
    for (int L = 0; L < 4; L++)
#pragma unroll
        for (int q = 0; q < 3; q++) lo[L][q] = 0;
#pragma unroll
    for (int step = 256; step > 0; step >>= 1) {
#pragma unroll
        for (int L = 0; L < 4; L++) {
#pragma unroll
            for (int q = 0; q < 3; q++) {
                int Mi = q + (q >= L ? 1 : 0);
                if (sk[Mi * 512 + lo[L][q] + step - 1] > mkey[L]) lo[L][q] += step;
            }
        }
    }
#pragma unroll
    for (int L = 0; L < 4; L++) {
        int mrank = tid;
#pragma unroll
        for (int q = 0; q < 3; q++) {
            int Mi = q + (q >= L ? 1 : 0);
            int c = lo[L][q];
            if (sk[Mi * 512 + c] > mkey[L]) c++;
            mrank += c;
        }
        int mpos = 2047 - (int)(unsigned)(mkey[L] & 0xFFFFFFFFull);
        unsigned mu = (unsigned)(mkey[L] >> 32);
        g_perm[sb][mrank] = mpos;
        g_svalid[sb][mrank] = mu != 0u ? 1 : 0;
        g_sscore[sb][mrank] = mu != 0u ? __uint_as_float(mu) : NINF;
    }
}

// ---------------- stage 3: rotated IoU suppression bitmask -----------------
__device__ float inter_area(float4 pA, float4 pB, float4 qA, float4 qB) {
    float px[8], py[8], ox[8], oy[8];
    px[0] = pA.x; py[0] = pA.y; px[1] = pA.z; py[1] = pA.w;
    px[2] = pB.x; py[2] = pB.y; px[3] = pB.z; py[3] = pB.w;
    float qx[4] = {qA.x, qA.z, qB.x, qB.z};
    float qy[4] = {qA.y, qA.w, qB.y, qB.w};
    int cnt = 4;
#pragma unroll
    for (int kk = 0; kk < 4; kk++) {
        float p1x = qx[kk], p1y = qy[kk];
        int k2 = (kk + 1) & 3;
        float ex = qx[k2] - p1x, ey = qy[k2] - p1y;
        int oc = 0;
        float d0 = ex * (py[0] - p1y) - ey * (px[0] - p1x);
        float dc = d0;
        for (int i = 0; i < cnt; i++) {
            int nx = (i + 1 < cnt) ? i + 1 : 0;
            float dn = (i + 1 < cnt) ? (ex * (py[i + 1] - p1y) - ey * (px[i + 1] - p1x)) : d0;
            bool ci = dc >= 0.f, ni = dn >= 0.f;
            if (ci) { ox[oc] = px[i]; oy[oc] = py[i]; oc++; }
            if (ci != ni) {
                float den = dc - dn;
                float tt = dc / ((den == 0.f) ? 1.f : den);
                ox[oc] = px[i] + tt * (px[nx] - px[i]);
                oy[oc] = py[i] + tt * (py[nx] - py[i]);
                oc++;
            }
            dc = dn;
        }
        cnt = oc;
        if (cnt == 0) break;
        for (int i = 0; i < cnt; i++) { px[i] = ox[i]; py[i] = oy[i]; }
    }
    if (cnt < 3) return 0.f;
    float s = 0.f;
    for (int i = 0; i < cnt; i++) {
        int nx = (i + 1 < cnt) ? i + 1 : 0;
        s += px[i] * py[nx] - px[nx] * py[i];
    }
    return 0.5f * fabsf(s);
}

__global__ __launch_bounds__(256) void mask_kernel() {
    int grp = threadIdx.x >> 6, lane = threadIdx.x & 63;
    int tile = blockIdx.x * 4 + grp;
    int img = tile / 528, tri = tile % 528;
    int rb = 0, rowrem = 32;
    while (tri >= rowrem) { tri -= rowrem; rowrem--; rb++; }
    int cb = rb + tri;

    __shared__ float4 sg[4][64][4];
    __shared__ int sperm[4][64];
    const float4* gg = (const float4*)&g_geom[img][0][0];
    sperm[grp][lane] = g_perm[img][cb * 64 + lane];
    int prow = g_perm[img][rb * 64 + lane];
    __syncthreads();
    for (int i = lane; i < 256; i += 64) {
        int box = i >> 2, k = i & 3;
        sg[grp][box][k] = gg[sperm[grp][box] * 4 + k];
    }
    __syncthreads();

    int row = rb * 64 + lane;
    float4 rA = gg[prow * 4 + 0];
    float4 rB = gg[prow * 4 + 1];
    float4 rC = gg[prow * 4 + 2];
    float4 rD = gg[prow * 4 + 3];

    unsigned long long surv = 0;
#pragma unroll 4
    for (int j = 0; j < 64; j++) {
        float4 cC = sg[grp][j][2];
        float ddx = rC.y - cC.y, ddy = rC.z - cC.z;
        float rr = rC.w + cC.w;
        float mn = fminf(rC.x, cC.x), mx = fmaxf(rC.x, cC.x);
        bool ok = (ddx * ddx + ddy * ddy < rr * rr) && (mn > 0.7f * mx);
        surv |= ((unsigned long long)ok) << j;
    }
    if (cb == rb) surv &= (lane < 63) ? (~0ull << (lane + 1)) : 0ull;

    unsigned long long bits = 0;
    while (surv) {
        int j = __ffsll((long long)surv) - 1;
        surv &= surv - 1;
        float4 cC = sg[grp][j][2];
        float4 cD = sg[grp][j][3];
        float S = rC.x + cC.x;
        float xl = fmaxf(rD.x, cD.x), xr = fminf(rD.y, cD.y);
        float yl = fmaxf(rD.z, cD.z), yr = fminf(rD.w, cD.w);
        float ub = fmaxf(xr - xl, 0.f) * fmaxf(yr - yl, 0.f);
        if (ub * 1.7f < S * 0.6993f) continue;
        float inter = inter_area(rA, rB, sg[grp][j][0], sg[grp][j][1]);
        float iou = inter / (S - inter + 1e-7f);
        if (iou > 0.7f) bits |= (1ull << j);
    }
    g_mask[img][row][cb] = bits;
    if (bits)
        atomicOr(&g_rowany[img][row >> 6], 1ull << (row & 63));
}

// ---------- stage 4: staged greedy (masks pre-staged in smem) --------------
__global__ __launch_bounds__(512) void greedy_out_kernel(float* __restrict__ out) {
    int b = blockIdx.x;
    int tid = threadIdx.x;
    __shared__ unsigned long long smask[SMAX][32];   // 40 KB staged source masks
    __shared__ int srcrow[SMAX];
    __shared__ unsigned long long s_ra[32];
    __shared__ unsigned long long s_remv[32];
    __shared__ int s_pfx[33];
    __shared__ int s_kpfx[33];
    __shared__ int s_S;

    // load rowany + source-count prefix
    if (tid < 32) s_ra[tid] = g_rowany[b][tid];
    __syncthreads();
    if (tid < 32) {
        int c = __popcll(s_ra[tid]);
        int p = c;
#pragma unroll
        for (int off = 1; off < 32; off <<= 1) {
            int v = __shfl_up_sync(0xffffffffu, p, off);
            if (tid >= off) p += v;
        }
        s_pfx[tid + 1] = p;
        if (tid == 0) s_pfx[0] = 0;
        if (tid == 31) s_S = (p < SMAX) ? p : SMAX;
    }
    __syncthreads();
    int S = s_S;
    // build compact source-row list (first SMAX sources in row order)
    for (int s = tid; s < S; s += 512) {
        int w = 0;
        while (s_pfx[w + 1] <= s) w++;
        srcrow[s] = w * 64 + sel64(s_ra[w], s - s_pfx[w]);
    }
    __syncthreads();
    // bulk-stage source mask rows into shared (coalesced)
    for (int e = tid; e < S * 32; e += 512)
        smask[e >> 5][e & 31] = g_mask[b][srcrow[e >> 5]][e & 31];
    __syncthreads();

    // serial greedy over sources only (warp 0); masks come from shared
    if (tid < 32) {
        int lane = tid;
        unsigned long long remv = 0;
        const unsigned long long* vp = (const unsigned long long*)&g_svalid[b][lane * 64];
#pragma unroll
        for (int q = 0; q < 8; q++) {
            unsigned long long w8 = vp[q];
#pragma unroll
            for (int kk = 0; kk < 8; kk++)
                if (((w8 >> (kk * 8)) & 0xffull) == 0ull)
                    remv |= (1ull << (q * 8 + kk));
        }
        int sidx = 0, keeps = 0;
        for (int c = 0; c < 32; c++) {
            unsigned long long raw = s_ra[c];
            while (raw) {
                int k = __ffsll((long long)raw) - 1;
                raw &= raw - 1;
                unsigned long long wbits = __shfl_sync(0xffffffffu, remv, c);
                if (!((wbits >> k) & 1ull)) {
                    remv |= (sidx < S) ? smask[sidx][lane]
                                       : __ldcg(&g_mask[b][c * 64 + k][lane]);
                }
                sidx++;
            }
            unsigned long long wfin = __shfl_sync(0xffffffffu, remv, c);
            keeps += __popcll(~wfin);
            if (keeps >= PRE) break;
        }
        s_remv[lane] = remv;
    }
    __syncthreads();
    // kept-bit prefix
    if (tid < 32) {
        int c = __popcll(~s_remv[tid]);
        int p = c;
#pragma unroll
        for (int off = 1; off < 32; off <<= 1) {
            int v = __shfl_up_sync(0xffffffffu, p, off);
            if (tid >= off) p += v;
        }
        s_kpfx[tid + 1] = p;
        if (tid == 0) s_kpfx[0] = 0;
    }
    __syncthreads();
    int total = s_kpfx[32];
    int n = total < PRE ? total : PRE;

    // parallel output select: slot tid -> tid-th kept row
    float v0 = 0, v1 = 0, v2 = 0, v3 = 0, v4 = 0, sc = 0;
    if (tid < n) {
        int w = 0;
        while (s_kpfx[w + 1] <= tid) w++;
        int i = w * 64 + sel64(~s_remv[w], tid - s_kpfx[w]);
        int pos = g_perm[b][i];
        v0 = g_box[b][pos][0]; v1 = g_box[b][pos][1];
        v2 = g_box[b][pos][2]; v3 = g_box[b][pos][3];
        v4 = g_box[b][pos][4];
        sc = g_sscore[b][i];
    }
    float* ob = out + ((long long)b * PRE + tid) * 5;
    ob[0] = v0; ob[1] = v1; ob[2] = v2; ob[3] = v3; ob[4] = v4;
    out[NB * PRE * 5 + b * PRE + tid] = sc;
}

extern "C" void kernel_launch(void* const* d_in, const int* in_sizes, int n_in,
                              void* d_out, int out_size) {
    const float* obj[4] = {0, 0, 0, 0};
    const float* dlt[4] = {0, 0, 0, 0};
    const float* anch = 0;
    const int osz[4] = {786432, 196608, 49152, 12288};
    const int dsz[4] = {4718592, 1179648, 294912, 73728};
    for (int i = 0; i < n_in; i++) {
        int s = in_sizes[i];
        const float* p = (const float*)d_in[i];
        if (s == 5222400) { anch = p; continue; }
        for (int l = 0; l < 4; l++) {
            if (s == osz[l]) obj[l] = p;
            else if (s == dsz[l]) dlt[l] = p;
        }
    }
    select_kernel<<<NBLK, 512>>>(obj[0], obj[1], obj[2], obj[3]);
    sortdecode_kernel<<<16, 512>>>(dlt[0], dlt[1], dlt[2], dlt[3], anch);
    mask_kernel<<<528, 256>>>();
    greedy_out_kernel<<<NB, 512>>>((float*)d_out);
}

// round 13
// speedup vs baseline: 2.1737x; 1.1010x over previous
#include <cuda_runtime.h>

#define NB 4
#define PRE 512
#define NC 2048
#define TANCH 261120
#define NBIN 4096
#define SHIFT 20
#define CANDCAP 2048
#define NBLK 264
#define SMAX 160
#define NINF __int_as_float(0xff800000)

// ---------------- scratch (device globals; zero-initialized) --------------
__device__ int g_ccnt[16];
__device__ int g_imgarr[NB];
__device__ unsigned long long g_rowany[NB][32];
__device__ unsigned long long g_cand[16][CANDCAP];
__device__ float g_box[NB][NC][5];                // pos-indexed
__device__ float g_score[NB][NC];                 // pos-indexed
__device__ unsigned char g_valid[NB][NC];         // pos-indexed
__device__ float g_geom[NB][NC][16];              // pos-indexed
__device__ unsigned long long g_key[NB][NC];
__device__ int g_perm[NB][NC];                    // sorted rank -> pos
__device__ unsigned char g_svalid[NB][NC];        // sorted order
__device__ float g_sscore[NB][NC];                // sorted order
__device__ unsigned long long g_mask[NB][NC][32];

__device__ const int c_aoff[4] = {0, 196608, 245760, 258048};
// static collect thresholds: ~top-900 quantile of N(0,1) per level size
// (exactness does NOT depend on these: out-of-range counts trigger the
//  exact in-kernel fallback below)
__device__ const float c_thr[4] = {2.605f, 2.090f, 1.4523f, 0.5446f};

__device__ __forceinline__ unsigned fflip(float f) {
    unsigned u = __float_as_uint(f);
    return (u & 0x80000000u) ? ~u : (u | 0x80000000u);
}
__device__ __forceinline__ float funflip(unsigned u) {
    return __uint_as_float((u & 0x80000000u) ? (u ^ 0x80000000u) : ~u);
}

__device__ __forceinline__ void map_block(int bx, int& b, int& lvl, int& c0, int& n) {
    b = bx / 66;
    int t = bx % 66;
    if (t < 48)      { lvl = 0; c0 = t * 4096;        n = 4096; }
    else if (t < 60) { lvl = 1; c0 = (t - 48) * 4096; n = 4096; }
    else if (t < 64) { lvl = 2; c0 = (t - 60) * 3072; n = 3072; }
    else             { lvl = 3; c0 = (t - 64) * 1536; n = 1536; }
}

// select the r-th (0-based) set bit of a 64-bit word
__device__ __forceinline__ int sel64(unsigned long long word, int r) {
    unsigned lo = (unsigned)word;
    int cl = __popc(lo);
    if (r < cl) return __fns(lo, 0, r + 1);
    return 32 + __fns((unsigned)(word >> 32), 0, r - cl + 1);
}

// ------------- stage 1: single-pass threshold collect ----------------------
__global__ __launch_bounds__(512) void select_kernel(const float* __restrict__ o0,
                                                     const float* __restrict__ o1,
                                                     const float* __restrict__ o2,
                                                     const float* __restrict__ o3) {
    int tid = threadIdx.x;
    int b, lvl, c0, n;
    map_block(blockIdx.x, b, lvl, c0, n);
    const float* base = lvl == 0 ? o0 : lvl == 1 ? o1 : lvl == 2 ? o2 : o3;
    int H = 256 >> lvl, HW = H * H;
    int NL = 3 * HW;
    int seg = b * 4 + lvl;
    float T = c_thr[lvl];
    const float4* p4 = (const float4*)(base + (long long)b * NL + c0);
    int n4 = n >> 2;
    for (int m = tid; m < n4; m += 512) {
        float4 v = p4[m];
        float vals[4] = {v.x, v.y, v.z, v.w};
#pragma unroll
        for (int s = 0; s < 4; s++) {
            if (vals[s] >= T) {
                unsigned u = fflip(vals[s]);
                int gm = c0 + m * 4 + s;
                int idx = (gm % HW) * 3 + gm / HW;   // (y*W+x)*A + a order
                int pos = atomicAdd(&g_ccnt[seg], 1);
                if (pos < CANDCAP)
                    g_cand[seg][pos] = (((unsigned long long)u) << 32) | (unsigned)(~idx);
            }
        }
    }
}

// -- stage 2: validate/sort -> top-512 -> decode + geometry; lvl0 merges ----
__global__ __launch_bounds__(512) void sortdecode_kernel(const float* __restrict__ o0,
                                                         const float* __restrict__ o1,
                                                         const float* __restrict__ o2,
                                                         const float* __restrict__ o3,
                                                         const float* __restrict__ d0,
                                                         const float* __restrict__ d1,
                                                         const float* __restrict__ d2,
                                                         const float* __restrict__ d3,
                                                         const float* __restrict__ anchors) {
    int seg = blockIdx.x;
    int sb = seg >> 2, slvl = seg & 3;
    __shared__ unsigned long long sk[CANDCAP];
    __shared__ int wtot[16], woff[16];
    __shared__ int s_tot;
    int tid = threadIdx.x;
    int sH = 256 >> slvl, sHW = sH * sH;
    int NL = 3 * sHW;

    int cnt = g_ccnt[seg];
    __syncthreads();
    if (tid == 0) g_ccnt[seg] = 0;

    if (cnt < PRE || cnt > CANDCAP) {
        // ---- exact fallback: full hist select for this segment ----
        const float* ob = slvl == 0 ? o0 : slvl == 1 ? o1 : slvl == 2 ? o2 : o3;
        const float* p = ob + (long long)sb * NL;
        int* h = (int*)sk;                        // reuse sort buffer as hist
        for (int i = tid; i < NBIN; i += 512) h[i] = 0;
        __syncthreads();
        for (int m = tid; m < NL; m += 512)
            atomicAdd(&h[fflip(p[m]) >> SHIFT], 1);
        __syncthreads();
        __shared__ unsigned s_fth;
        if (tid == 0) {
            int cum = 0, bin = NBIN - 1;
            for (; bin > 0; bin--) { cum += h[bin]; if (cum >= PRE) break; }
            s_fth = (unsigned)bin;
        }
        __syncthreads();
        unsigned fth = s_fth;
        for (int m = tid; m < NL; m += 512) {
            unsigned u = fflip(p[m]);
            if ((u >> SHIFT) >= fth) {
                int idx = (m % sHW) * 3 + m / sHW;
                int pp = atomicAdd(&g_ccnt[seg], 1);
                if (pp < CANDCAP)
                    g_cand[seg][pp] = (((unsigned long long)u) << 32) | (unsigned)(~idx);
            }
        }
        __threadfence();
        __syncthreads();
        cnt = g_ccnt[seg];
        if (cnt > CANDCAP) cnt = CANDCAP;
        __syncthreads();
        if (tid == 0) g_ccnt[seg] = 0;
        __syncthreads();
    }

    int M = (cnt <= 1024) ? 1024 : CANDCAP;
    for (int i = tid; i < M; i += 512)
        sk[i] = (i < cnt) ? g_cand[seg][i] : 0ull;
    __syncthreads();
    for (int ksz = 2; ksz <= M; ksz <<= 1) {
        for (int j = ksz >> 1; j > 0; j >>= 1) {
            for (int i = tid; i < M; i += 512) {
                int l = i ^ j;
                if (l > i) {
                    unsigned long long a = sk[i], c = sk[l];
                    bool desc = ((i & ksz) == 0);
                    if (desc ? (a < c) : (a > c)) { sk[i] = c; sk[l] = a; }
                }
            }
            __syncthreads();
        }
    }
    unsigned long long kk = sk[tid];
    float val = funflip((unsigned)(kk >> 32));
    int li = (int)(~(unsigned)(kk & 0xFFFFFFFFull));
    int a = li % 3, cell = li / 3;
    int x = cell % sH, y = cell / sH;
    const float* dl = slvl == 0 ? d0 : slvl == 1 ? d1 : slvl == 2 ? d2 : d3;
    long long bi = ((long long)sb * 18 + a * 6) * sHW + (long long)y * sH + x;
    float dx = dl[bi], dy = dl[bi + sHW], dw = dl[bi + 2LL * sHW],
          dh = dl[bi + 3LL * sHW], ds = dl[bi + 4LL * sHW], dc = dl[bi + 5LL * sHW];
    int ta = c_aoff[slvl] + li;
    const float* an = anchors + ((long long)sb * TANCH + ta) * 5;
    float ax = an[0], ay = an[1], aw = an[2], ah = an[3], aa = an[4];
    const float LOGM = 4.135166556742356f;
    dw = fminf(dw, LOGM);
    dh = fminf(dh, LOGM);
    float bw = aw * expf(dw), bh = ah * expf(dh);
    float bcx = ax + dx * aw, bcy = ay + dy * ah;
    float ang = aa + atan2f(ds, dc);
    float sc = 0.5f + 0.5f * tanhf(0.5f * val);       // XLA logistic form
    bool vd = (bw >= 1e-3f) && (bh >= 1e-3f) && (sc >= 0.0f);

    // stable compaction: valids to front, invalids to tail
    unsigned bal = __ballot_sync(0xffffffffu, vd);
    int lane = tid & 31, w = tid >> 5;
    int prew = __popc(bal & ((1u << lane) - 1u));
    if (lane == 0) wtot[w] = __popc(bal);
    __syncthreads();
    if (tid == 0) {
        int s = 0;
        for (int q = 0; q < 16; q++) { woff[q] = s; s += wtot[q]; }
        s_tot = s;
    }
    __syncthreads();
    int vbefore = woff[w] + prew;
    int rank = vd ? vbefore : (s_tot + (tid - vbefore));
    int pos = slvl * PRE + rank;

    g_box[sb][pos][0] = bcx; g_box[sb][pos][1] = bcy;
    g_box[sb][pos][2] = bw;  g_box[sb][pos][3] = bh;
    g_box[sb][pos][4] = ang;
    g_score[sb][pos] = sc;
    g_valid[sb][pos] = vd ? 1 : 0;
    unsigned u = vd ? __float_as_uint(sc) : 0u;       // score desc, pos asc tiebreak
    g_key[sb][pos] = (((unsigned long long)u) << 32) | (unsigned)(2047 - pos);

    {
        float off = 8192.0f * (float)slvl;
        float cx = bcx + off, cy = bcy + off;
        float ca = cosf(ang), sa = sinf(ang);
        float hw = 0.5f * bw, hh = 0.5f * bh;
        float dxs[4] = {hw, -hw, -hw, hw};
        float dys[4] = {hh, hh, -hh, -hh};
        float xmn = 1e30f, xmx = -1e30f, ymn = 1e30f, ymx = -1e30f;
        float* gp = &g_geom[sb][pos][0];
#pragma unroll
        for (int c = 0; c < 4; c++) {
            float xx = cx + dxs[c] * ca - dys[c] * sa;
            float yy = cy + dxs[c] * sa + dys[c] * ca;
            gp[2 * c] = xx;
            gp[2 * c + 1] = yy;
            xmn = fminf(xmn, xx); xmx = fmaxf(xmx, xx);
            ymn = fminf(ymn, yy); ymx = fmaxf(ymx, yy);
        }
        gp[8] = bw * bh;
        gp[9] = cx;
        gp[10] = cy;
        gp[11] = 0.5f * sqrtf(bw * bw + bh * bh);
        gp[12] = xmn;
        gp[13] = xmx;
        gp[14] = ymn;
        gp[15] = ymx;
    }

    // ---- publish this segment's run, then slvl==0 block merges the image --
    __threadfence();
    __syncthreads();
    if (tid == 0) atomicAdd(&g_imgarr[sb], 1);
    if (slvl != 0) return;
    if (tid == 0) {
        while (atomicAdd(&g_imgarr[sb], 0) < 4) {}
        g_imgarr[sb] = 0;
        __threadfence();
    }
    __syncthreads();
    if (tid < 32) g_rowany[sb][tid] = 0ull;
    for (int i = tid; i < NC; i += 512) sk[i] = __ldcg(&g_key[sb][i]);
    __syncthreads();

    // rank-scatter merge: 12 lockstep descending-count binary searches
    unsigned long long mkey[4];
#pragma unroll
    for (int L = 0; L < 4; L++) mkey[L] = sk[L * 512 + tid];
    int lo[4][3];
#pragma unroll
    for (int L = 0; L < 4; L++)
#pragma unroll
        for (int q = 0; q < 3; q++) lo[L][q] = 0;
#pragma unroll
    for (int step = 256; step > 0; step >>= 1) {
#pragma unroll
        for (int L = 0; L < 4; L++) {
#pragma unroll
            for (int q = 0; q < 3; q++) {
                int Mi = q + (q >= L ? 1 : 0);
                if (sk[Mi * 512 + lo[L][q] + step - 1] > mkey[L]) lo[L][q] += step;
            }
        }
    }
#pragma unroll
    for (int L = 0; L < 4; L++) {
        int mrank = tid;
#pragma unroll
        for (int q = 0; q < 3; q++) {
            int Mi = q + (q >= L ? 1 : 0);
            int c = lo[L][q];
            if (sk[Mi * 512 + c] > mkey[L]) c++;
            mrank += c;
        }
        int mpos = 2047 - (int)(unsigned)(mkey[L] & 0xFFFFFFFFull);
        unsigned mu = (unsigned)(mkey[L] >> 32);
        g_perm[sb][mrank] = mpos;
        g_svalid[sb][mrank] = mu != 0u ? 1 : 0;
        g_sscore[sb][mrank] = mu != 0u ? __uint_as_float(mu) : NINF;
    }
}

// ---------------- stage 3: rotated IoU suppression bitmask -----------------
__device__ float inter_area(float4 pA, float4 pB, float4 qA, float4 qB) {
    float px[8], py[8], ox[8], oy[8];
    px[0] = pA.x; py[0] = pA.y; px[1] = pA.z; py[1] = pA.w;
    px[2] = pB.x; py[2] = pB.y; px[3] = pB.z; py[3] = pB.w;
    float qx[4] = {qA.x, qA.z, qB.x, qB.z};
    float qy[4] = {qA.y, qA.w, qB.y, qB.w};
    int cnt = 4;
#pragma unroll
    for (int kk = 0; kk < 4; kk++) {
        float p1x = qx[kk], p1y = qy[kk];
        int k2 = (kk + 1) & 3;
        float ex = qx[k2] - p1x, ey = qy[k2] - p1y;
        int oc = 0;
        float d0 = ex * (py[0] - p1y) - ey * (px[0] - p1x);
        float dc = d0;
        for (int i = 0; i < cnt; i++) {
            int nx = (i + 1 < cnt) ? i + 1 : 0;
            float dn = (i + 1 < cnt) ? (ex * (py[i + 1] - p1y) - ey * (px[i + 1] - p1x)) : d0;
            bool ci = dc >= 0.f, ni = dn >= 0.f;
            if (ci) { ox[oc] = px[i]; oy[oc] = py[i]; oc++; }
            if (ci != ni) {
                float den = dc - dn;
                float tt = dc / ((den == 0.f) ? 1.f : den);
                ox[oc] = px[i] + tt * (px[nx] - px[i]);
                oy[oc] = py[i] + tt * (py[nx] - py[i]);
                oc++;
            }
            dc = dn;
        }
        cnt = oc;
        if (cnt == 0) break;
        for (int i = 0; i < cnt; i++) { px[i] = ox[i]; py[i] = oy[i]; }
    }
    if (cnt < 3) return 0.f;
    float s = 0.f;
    for (int i = 0; i < cnt; i++) {
        int nx = (i + 1 < cnt) ? i + 1 : 0;
        s += px[i] * py[nx] - px[nx] * py[i];
    }
    return 0.5f * fabsf(s);
}

__global__ __launch_bounds__(256) void mask_kernel() {
    int grp = threadIdx.x >> 6, lane = threadIdx.x & 63;
    int tile = blockIdx.x * 4 + grp;
    int img = tile / 528, tri = tile % 528;
    int rb = 0, rowrem = 32;
    while (tri >= rowrem) { tri -= rowrem; rowrem--; rb++; }
    int cb = rb + tri;

    __shared__ float4 sg[4][64][4];
    __shared__ int sperm[4][64];
    const float4* gg = (const float4*)&g_geom[img][0][0];
    sperm[grp][lane] = g_perm[img][cb * 64 + lane];
    int prow = g_perm[img][rb * 64 + lane];
    __syncthreads();
    for (int i = lane; i < 256; i += 64) {
        int box = i >> 2, k = i & 3;
        sg[grp][box][k] = gg[sperm[grp][box] * 4 + k];
    }
    __syncthreads();

    int row = rb * 64 + lane;
    float4 rA = gg[prow * 4 + 0];
    float4 rB = gg[prow * 4 + 1];
    float4 rC = gg[prow * 4 + 2];
    float4 rD = gg[prow * 4 + 3];

    unsigned long long surv = 0;
#pragma unroll 4
    for (int j = 0; j < 64; j++) {
        float4 cC = sg[grp][j][2];
        float ddx = rC.y - cC.y, ddy = rC.z - cC.z;
        float rr = rC.w + cC.w;
        float mn = fminf(rC.x, cC.x), mx = fmaxf(rC.x, cC.x);
        bool ok = (ddx * ddx + ddy * ddy < rr * rr) && (mn > 0.7f * mx);
        surv |= ((unsigned long long)ok) << j;
    }
    if (cb == rb) surv &= (lane < 63) ? (~0ull << (lane + 1)) : 0ull;

    unsigned long long bits = 0;
    while (surv) {
        int j = __ffsll((long long)surv) - 1;
        surv &= surv - 1;
        float4 cC = sg[grp][j][2];
        float4 cD = sg[grp][j][3];
        float S = rC.x + cC.x;
        float xl = fmaxf(rD.x, cD.x), xr = fminf(rD.y, cD.y);
        float yl = fmaxf(rD.z, cD.z), yr = fminf(rD.w, cD.w);
        float ub = fmaxf(xr - xl, 0.f) * fmaxf(yr - yl, 0.f);
        if (ub * 1.7f < S * 0.6993f) continue;
        float inter = inter_area(rA, rB, sg[grp][j][0], sg[grp][j][1]);
        float iou = inter / (S - inter + 1e-7f);
        if (iou > 0.7f) bits |= (1ull << j);
    }
    g_mask[img][row][cb] = bits;
    if (bits)
        atomicOr(&g_rowany[img][row >> 6], 1ull << (row & 63));
}

// ---------- stage 4: staged greedy (masks pre-staged in smem) --------------
__global__ __launch_bounds__(512) void greedy_out_kernel(float* __restrict__ out) {
    int b = blockIdx.x;
    int tid = threadIdx.x;
    __shared__ unsigned long long smask[SMAX][32];   // 40 KB staged source masks
    __shared__ int srcrow[SMAX];
    __shared__ unsigned long long s_ra[32];
    __shared__ unsigned long long s_remv[32];
    __shared__ int s_pfx[33];
    __shared__ int s_kpfx[33];
    __shared__ int s_S;

    if (tid < 32) s_ra[tid] = g_rowany[b][tid];
    __syncthreads();
    if (tid < 32) {
        int c = __popcll(s_ra[tid]);
        int p = c;
#pragma unroll
        for (int off = 1; off < 32; off <<= 1) {
            int v = __shfl_up_sync(0xffffffffu, p, off);
            if (tid >= off) p += v;
        }
        s_pfx[tid + 1] = p;
        if (tid == 0) s_pfx[0] = 0;
        if (tid == 31) s_S = (p < SMAX) ? p : SMAX;
    }
    __syncthreads();
    int S = s_S;
    for (int s = tid; s < S; s += 512) {
        int w = 0;
        while (s_pfx[w + 1] <= s) w++;
        srcrow[s] = w * 64 + sel64(s_ra[w], s - s_pfx[w]);
    }
    __syncthreads();
    for (int e = tid; e < S * 32; e += 512)
        smask[e >> 5][e & 31] = g_mask[b][srcrow[e >> 5]][e & 31];
    __syncthreads();

    if (tid < 32) {
        int lane = tid;
        unsigned long long remv = 0;
        const unsigned long long* vp = (const unsigned long long*)&g_svalid[b][lane * 64];
#pragma unroll
        for (int q = 0; q < 8; q++) {
            unsigned long long w8 = vp[q];
#pragma unroll
            for (int kk = 0; kk < 8; kk++)
                if (((w8 >> (kk * 8)) & 0xffull) == 0ull)
                    remv |= (1ull << (q * 8 + kk));
        }
        int sidx = 0, keeps = 0;
        for (int c = 0; c < 32; c++) {
            unsigned long long raw = s_ra[c];
            while (raw) {
                int k = __ffsll((long long)raw) - 1;
                raw &= raw - 1;
                unsigned long long wbits = __shfl_sync(0xffffffffu, remv, c);
                if (!((wbits >> k) & 1ull)) {
                    remv |= (sidx < S) ? smask[sidx][lane]
                                       : __ldcg(&g_mask[b][c * 64 + k][lane]);
                }
                sidx++;
            }
            unsigned long long wfin = __shfl_sync(0xffffffffu, remv, c);
            keeps += __popcll(~wfin);
            if (keeps >= PRE) break;
        }
        s_remv[lane] = remv;
    }
    __syncthreads();
    if (tid < 32) {
        int c = __popcll(~s_remv[tid]);
        int p = c;
#pragma unroll
        for (int off = 1; off < 32; off <<= 1) {
            int v = __shfl_up_sync(0xffffffffu, p, off);
            if (tid >= off) p += v;
        }
        s_kpfx[tid + 1] = p;
        if (tid == 0) s_kpfx[0] = 0;
    }
    __syncthreads();
    int total = s_kpfx[32];
    int n = total < PRE ? total : PRE;

    float v0 = 0, v1 = 0, v2 = 0, v3 = 0, v4 = 0, sc = 0;
    if (tid < n) {
        int w = 0;
        while (s_kpfx[w + 1] <= tid) w++;
        int i = w * 64 + sel64(~s_remv[w], tid - s_kpfx[w]);
        int pos = g_perm[b][i];
        v0 = g_box[b][pos][0]; v1 = g_box[b][pos][1];
        v2 = g_box[b][pos][2]; v3 = g_box[b][pos][3];
        v4 = g_box[b][pos][4];
        sc = g_sscore[b][i];
    }
    float* ob = out + ((long long)b * PRE + tid) * 5;
    ob[0] = v0; ob[1] = v1; ob[2] = v2; ob[3] = v3; ob[4] = v4;
    out[NB * PRE * 5 + b * PRE + tid] = sc;
}

extern "C" void kernel_launch(void* const* d_in, const int* in_sizes, int n_in,
                              void* d_out, int out_size) {
    const float* obj[4] = {0, 0, 0, 0};
    const float* dlt[4] = {0, 0, 0, 0};
    const float* anch = 0;
    const int osz[4] = {786432, 196608, 49152, 12288};
    const int dsz[4] = {4718592, 1179648, 294912, 73728};
    for (int i = 0; i < n_in; i++) {
        int s = in_sizes[i];
        const float* p = (const float*)d_in[i];
        if (s == 5222400) { anch = p; continue; }
        for (int l = 0; l < 4; l++) {
            if (s == osz[l]) obj[l] = p;
            else if (s == dsz[l]) dlt[l] = p;
        }
    }
    select_kernel<<<NBLK, 512>>>(obj[0], obj[1], obj[2], obj[3]);
    sortdecode_kernel<<<16, 512>>>(obj[0], obj[1], obj[2], obj[3],
                                   dlt[0], dlt[1], dlt[2], dlt[3], anch);
    mask_kernel<<<528, 256>>>();
    greedy_out_kernel<<<NB, 512>>>((float*)d_out);
}